// round 9
// baseline (speedup 1.0000x reference)
#include <cuda_runtime.h>
#include <math.h>

#define NN   1024
#define DNF  128
#define G3   384
#define SLD  132     // A-tile smem stride: 128 k-floats + 4 pad
#define GLD  388     // gate buffer stride: 384 + 4 pad
#define GB_LD 132

// ---------------- device scratch ----------------
__device__ float g_er  [NN * DNF];
__device__ float g_cei [NN * G3];      // er @ wie^T + bvec (layer-invariant)
__device__ float g_gh  [NN * G3];      // gh + b_hh (per layer)
__device__ float g_ha  [NN * DNF];
__device__ float g_hb  [NN * DNF];
__device__ float g_wimP[16 * 48 * 64]; // packed tf32 frags: (w_ih@w_msg_h), K=128,N=384
__device__ float g_wieP[16 * 48 * 64];
__device__ float g_whhP[16 * 48 * 64];
__device__ float g_wgP [32 * 16 * 64]; // w_gate, K=256, N=128
__device__ float g_woP [32 * 16 * 64];
__device__ float g_bvec[G3];
__device__ int   g_nzi [NN * NN];
__device__ float g_nzv [NN * NN];
__device__ int   g_nzc [NN];
__device__ float g_part[64 * DNF];
__device__ int   g_flag[64];
__device__ int   g_rc;

// ---------------- helpers ----------------
__device__ __forceinline__ float to_tf32(float x) {
    float r; asm("cvt.rna.tf32.f32 %0, %1;" : "=f"(r) : "f"(x)); return r;
}
__device__ __forceinline__ float sigf(float x) { return 1.0f / (1.0f + expf(-x)); }

__device__ __forceinline__ void mma_tf32(float* c, const unsigned* a,
                                         unsigned b0, unsigned b1) {
    asm volatile(
        "mma.sync.aligned.m16n8k8.row.col.f32.tf32.tf32.f32 "
        "{%0,%1,%2,%3}, {%4,%5,%6,%7}, {%8,%9}, {%0,%1,%2,%3};"
        : "+f"(c[0]), "+f"(c[1]), "+f"(c[2]), "+f"(c[3])
        : "r"(a[0]), "r"(a[1]), "r"(a[2]), "r"(a[3]), "r"(b0), "r"(b1));
}

// packed fragment index for W[N][K] (k-major rows)
__device__ __forceinline__ int pidx(int n, int k, int nfr) {
    int n8 = n >> 3, q = n & 7, k8 = k >> 3, kk = k & 7;
    int half = kk >> 2, r = kk & 3;
    return ((k8 * nfr + n8) * 32 + q * 4 + r) * 2 + half;
}

// nz-list broadcast: first 64 entries register-cached per warp
__device__ __forceinline__ void get_nz(int k, int i0, int i1, float v0, float v1,
                                       const int* gip, const float* gvp,
                                       int& j, float& v) {
    if (k < 32)      { j = __shfl_sync(0xffffffffu, i0, k);      v = __shfl_sync(0xffffffffu, v0, k); }
    else if (k < 64) { j = __shfl_sync(0xffffffffu, i1, k - 32); v = __shfl_sync(0xffffffffu, v1, k - 32); }
    else             { j = gip[k]; v = gvp[k]; }
}

// full-row warp gather, 8 loads in flight
__device__ __forceinline__ float4 warp_gather8(const float* __restrict__ src,
                                               const int* gip, const float* gvp,
                                               int cnt, int lane) {
    int i0 = 0, i1 = 0; float v0 = 0.f, v1 = 0.f;
    if (lane < cnt)      { i0 = gip[lane];      v0 = gvp[lane]; }
    if (32 + lane < cnt) { i1 = gip[32 + lane]; v1 = gvp[32 + lane]; }
    float4 acc = make_float4(0.f, 0.f, 0.f, 0.f);
    int k = 0;
    for (; k + 8 <= cnt; k += 8) {
        int jj[8]; float ww[8];
#pragma unroll
        for (int u = 0; u < 8; u++) get_nz(k + u, i0, i1, v0, v1, gip, gvp, jj[u], ww[u]);
        float4 av[8];
#pragma unroll
        for (int u = 0; u < 8; u++)
            av[u] = *(const float4*)(src + (size_t)jj[u] * DNF + lane * 4);
#pragma unroll
        for (int u = 0; u < 8; u++) {
            acc.x += ww[u] * av[u].x; acc.y += ww[u] * av[u].y;
            acc.z += ww[u] * av[u].z; acc.w += ww[u] * av[u].w;
        }
    }
    for (; k < cnt; k++) {
        int j; float w;
        get_nz(k, i0, i1, v0, v1, gip, gvp, j, w);
        float4 av = *(const float4*)(src + (size_t)j * DNF + lane * 4);
        acc.x += w*av.x; acc.y += w*av.y; acc.z += w*av.z; acc.w += w*av.w;
    }
    return acc;
}

// ---------------------------------------------------------------------------
// k_setup: bid<1024 — adjacency compaction + er; bid>=1024 — weight
// products (wim, wie), packing (whh, wgate, wout), bvec.   256 threads.
// ---------------------------------------------------------------------------
__global__ void __launch_bounds__(256)
k_setup(const float* __restrict__ adj, const float* __restrict__ e,
        const float* __restrict__ w_msg_h, const float* __restrict__ w_msg_e,
        const float* __restrict__ w_ih, const float* __restrict__ b_msg,
        const float* __restrict__ w_hh, const float* __restrict__ w_gate,
        const float* __restrict__ w_out) {
    const int bid = blockIdx.x;
    const int tid = threadIdx.x;

    if (bid < NN) {
        const int i    = bid;
        const int lane = tid & 31;
        const int w    = tid >> 5;

        __shared__ int   s_idx[NN];
        __shared__ float s_val[NN];
        __shared__ int   s_wcnt[8];
        __shared__ int   s_woff[8];
        __shared__ int   s_cnt;
        __shared__ float s_red[8 * DNF];

        const float* arow = adj + (size_t)i * NN;
        const int base = w * 128;

        float av[4]; unsigned mm[4];
#pragma unroll
        for (int c = 0; c < 4; c++) av[c] = arow[base + c * 32 + lane];
        int tot = 0;
#pragma unroll
        for (int c = 0; c < 4; c++) {
            mm[c] = __ballot_sync(0xffffffffu, av[c] != 0.0f);
            tot += __popc(mm[c]);
        }
        if (lane == 0) s_wcnt[w] = tot;
        __syncthreads();
        if (tid == 0) {
            int run = 0;
            for (int ww = 0; ww < 8; ww++) { s_woff[ww] = run; run += s_wcnt[ww]; }
            s_cnt = run;
        }
        __syncthreads();

        int off = s_woff[w];
        const unsigned lm = (1u << lane) - 1u;
#pragma unroll
        for (int c = 0; c < 4; c++) {
            if (av[c] != 0.0f) {
                int p = off + __popc(mm[c] & lm);
                s_idx[p] = base + c * 32 + lane;
                s_val[p] = av[c];
            }
            off += __popc(mm[c]);
        }
        __syncthreads();

        const int cnt = s_cnt;
        if (tid == 0) g_nzc[i] = cnt;
        for (int k = tid; k < cnt; k += 256) {
            g_nzi[(size_t)i * NN + k] = s_idx[k];
            g_nzv[(size_t)i * NN + k] = s_val[k];
        }

        const int q = tid & 31;
        const int g = tid >> 5;
        const float* ebase = e + (size_t)i * NN * DNF;
        float4 acc = make_float4(0.f, 0.f, 0.f, 0.f);
        for (int k = g; k < cnt; k += 8) {
            float v = s_val[k];
            float4 ev = *(const float4*)(ebase + (size_t)s_idx[k] * DNF + q * 4);
            acc.x += v * ev.x; acc.y += v * ev.y;
            acc.z += v * ev.z; acc.w += v * ev.w;
        }
        s_red[g * DNF + q * 4 + 0] = acc.x;
        s_red[g * DNF + q * 4 + 1] = acc.y;
        s_red[g * DNF + q * 4 + 2] = acc.z;
        s_red[g * DNF + q * 4 + 3] = acc.w;
        __syncthreads();
        if (tid < 128) {
            float s = 0.f;
#pragma unroll
            for (int gg = 0; gg < 8; gg++) s += s_red[gg * DNF + tid];
            g_er[(size_t)i * DNF + tid] = s;
        }
        return;
    }

    const int sid = bid - NN;
    if (sid < 384) {
        const bool is_h = (sid < 192);
        const int  lsid = is_h ? sid : sid - 192;
        const float* B = is_h ? w_msg_h : w_msg_e;
        float* P = is_h ? g_wimP : g_wieP;
        int id = lsid * 256 + tid;
        int n = id >> 7, k = id & 127;
        float acc = 0.f;
        const float* wr = w_ih + (size_t)n * DNF;
#pragma unroll 4
        for (int d = 0; d < DNF; d++) acc += wr[d] * B[(size_t)d * DNF + k];
        P[pidx(n, k, 48)] = to_tf32(acc);
    } else if (sid < 432) {
        int b = sid - 384;
#pragma unroll
        for (int rep = 0; rep < 4; rep++) {
            int eid = b * 1024 + rep * 256 + tid;
            int n = eid >> 7, k = eid & 127;
            g_whhP[pidx(n, k, 48)] = to_tf32(w_hh[(size_t)n * DNF + k]);
        }
    } else if (sid < 464) {
        int b = sid - 432;
#pragma unroll
        for (int rep = 0; rep < 4; rep++) {
            int eid = b * 1024 + rep * 256 + tid;
            int n = eid >> 8, k = eid & 255;
            g_wgP[pidx(n, k, 16)] = to_tf32(w_gate[(size_t)n * 256 + k]);
        }
    } else if (sid < 496) {
        int b = sid - 464;
#pragma unroll
        for (int rep = 0; rep < 4; rep++) {
            int eid = b * 1024 + rep * 256 + tid;
            int n = eid >> 8, k = eid & 255;
            g_woP[pidx(n, k, 16)] = to_tf32(w_out[(size_t)n * 256 + k]);
        }
    } else {
        for (int n = tid; n < G3; n += 256) {
            float acc = 0.f;
            const float* wr = w_ih + (size_t)n * DNF;
            for (int k = 0; k < DNF; k++) acc += wr[k] * b_msg[k];
            g_bvec[n] = acc;
        }
    }
}

// ---------------------------------------------------------------------------
// k_cei: cei = er @ wie^T + bvec.  64 blocks x 1024 threads.
// ---------------------------------------------------------------------------
__global__ void __launch_bounds__(1024)
k_cei() {
    __shared__ float sA[16 * SLD];
    __shared__ float red[16 * 32 * 13];

    const int tid  = threadIdx.x;
    const int lane = tid & 31;
    const int w    = tid >> 5;        // 32 warps
    const int nw   = w & 15;
    const int kh   = w >> 4;
    const int q    = lane >> 2, r = lane & 3;
    const int r0   = blockIdx.x * 16;

#pragma unroll
    for (int rep = 0; rep < 2; rep++) {
        int eid = tid + rep * 1024;
        int i = eid >> 7, d = eid & 127;
        sA[i * SLD + d] = to_tf32(g_er[(size_t)(r0 + i) * DNF + d]);
    }
    __syncthreads();

    float acc[3][4];
#pragma unroll
    for (int j = 0; j < 3; j++)
#pragma unroll
        for (int c = 0; c < 4; c++) acc[j][c] = 0.f;

    const float2* bp = (const float2*)g_wieP;

    float2 bf[2][3];
#pragma unroll
    for (int j = 0; j < 3; j++)
        bf[0][j] = bp[((kh * 8) * 48 + nw * 3 + j) * 32 + lane];

#pragma unroll
    for (int kk = 0; kk < 8; kk++) {
        const int k8 = kh * 8 + kk;
        const int cur = kk & 1, nxt = cur ^ 1;
        if (kk < 7) {
#pragma unroll
            for (int j = 0; j < 3; j++)
                bf[nxt][j] = bp[((k8 + 1) * 48 + nw * 3 + j) * 32 + lane];
        }
        const int ko = k8 * 8;
        unsigned a[4];
        a[0] = __float_as_uint(sA[q * SLD + ko + r]);
        a[1] = __float_as_uint(sA[(q + 8) * SLD + ko + r]);
        a[2] = __float_as_uint(sA[q * SLD + ko + r + 4]);
        a[3] = __float_as_uint(sA[(q + 8) * SLD + ko + r + 4]);
#pragma unroll
        for (int j = 0; j < 3; j++)
            mma_tf32(acc[j], a, __float_as_uint(bf[cur][j].x),
                               __float_as_uint(bf[cur][j].y));
    }

    if (kh == 1) {
        float* rp = red + (nw * 32 + lane) * 13;
#pragma unroll
        for (int j = 0; j < 3; j++)
#pragma unroll
            for (int c = 0; c < 4; c++) rp[j * 4 + c] = acc[j][c];
    }
    __syncthreads();
    if (kh == 0) {
        const float* rp = red + (nw * 32 + lane) * 13;
#pragma unroll
        for (int j = 0; j < 3; j++) {
#pragma unroll
            for (int c = 0; c < 4; c++) acc[j][c] += rp[j * 4 + c];
            int col = (nw * 3 + j) * 8 + 2 * r;
            float bv0 = g_bvec[col], bv1 = g_bvec[col + 1];
            *(float2*)(g_cei + (size_t)(r0 + q) * G3 + col) =
                make_float2(acc[j][0] + bv0, acc[j][1] + bv1);
            *(float2*)(g_cei + (size_t)(r0 + q + 8) * G3 + col) =
                make_float2(acc[j][2] + bv0, acc[j][3] + bv1);
        }
    }
}

// ---------------------------------------------------------------------------
// k_layer: 128 cooperating blocks x 512 threads.
//   blocks 0..63   (gh): h-tile -> gh GEMM -> g_gh global -> flag(epoch)
//   blocks 64..127 (gi): gather -> gi GEMM -> +cei+b_ih in smem ->
//                        spin on flag -> GRU (gh from L2) -> hnext
// All 128 blocks co-resident (128 < 148 SMs) => spin is deadlock-free.
// Epochs 1..4 are collision-free across graph replays (flag holds the
// previous layer's epoch when a layer starts).
// ---------------------------------------------------------------------------
__global__ void __launch_bounds__(512)
k_layer(const float* __restrict__ hprev, float* __restrict__ hnext,
        const float* __restrict__ b_ih, const float* __restrict__ b_hh,
        int epoch) {
    __shared__ float sA[16 * SLD];
    __shared__ float G[16 * GLD];     // gi block only

    const int tid  = threadIdx.x;
    const int lane = tid & 31;
    const int w    = tid >> 5;        // 16 warps
    const int q    = lane >> 2, r = lane & 3;
    const bool is_gh = (blockIdx.x < 64);
    const int b  = is_gh ? blockIdx.x : blockIdx.x - 64;
    const int r0 = b * 16;

    // ---- stage A tile ----
    {
        const int row = r0 + w;
        if (is_gh) {
            float4 hv = *(const float4*)(hprev + (size_t)row * DNF + lane * 4);
            float* d = sA + w * SLD + lane * 4;
            d[0] = to_tf32(hv.x); d[1] = to_tf32(hv.y);
            d[2] = to_tf32(hv.z); d[3] = to_tf32(hv.w);
        } else {
            const int cnt = g_nzc[row];
            const int*   gip = g_nzi + (size_t)row * NN;
            const float* gvp = g_nzv + (size_t)row * NN;
            float4 acc = warp_gather8(hprev, gip, gvp, cnt, lane);
            float* d = sA + w * SLD + lane * 4;
            d[0] = to_tf32(acc.x); d[1] = to_tf32(acc.y);
            d[2] = to_tf32(acc.z); d[3] = to_tf32(acc.w);
        }
    }
    __syncthreads();

    // ---- GEMM: 16 n-warps x 3 frags, K=128, prefetch depth 2 ----
    const float2* bp = (const float2*)(is_gh ? g_whhP : g_wimP);

    float acc[3][4];
#pragma unroll
    for (int j = 0; j < 3; j++)
#pragma unroll
        for (int c = 0; c < 4; c++) acc[j][c] = 0.f;

    float2 bf[2][3];
#pragma unroll
    for (int j = 0; j < 3; j++) {
        bf[0][j] = bp[(0 * 48 + w * 3 + j) * 32 + lane];
        bf[1][j] = bp[(1 * 48 + w * 3 + j) * 32 + lane];
    }

#pragma unroll
    for (int k8 = 0; k8 < 16; k8++) {
        float2 nx[3];
        if (k8 < 14) {
#pragma unroll
            for (int j = 0; j < 3; j++)
                nx[j] = bp[((k8 + 2) * 48 + w * 3 + j) * 32 + lane];
        }
        const int ko = k8 * 8;
        unsigned a[4];
        a[0] = __float_as_uint(sA[q * SLD + ko + r]);
        a[1] = __float_as_uint(sA[(q + 8) * SLD + ko + r]);
        a[2] = __float_as_uint(sA[q * SLD + ko + r + 4]);
        a[3] = __float_as_uint(sA[(q + 8) * SLD + ko + r + 4]);
        const int cur = k8 & 1;
#pragma unroll
        for (int j = 0; j < 3; j++)
            mma_tf32(acc[j], a, __float_as_uint(bf[cur][j].x),
                               __float_as_uint(bf[cur][j].y));
        if (k8 < 14) {
#pragma unroll
            for (int j = 0; j < 3; j++) bf[cur][j] = nx[j];
        }
    }

    if (is_gh) {
        // ---- write gh + b_hh to global; signal ----
#pragma unroll
        for (int j = 0; j < 3; j++) {
            int col = (w * 3 + j) * 8 + 2 * r;
            float b0 = b_hh[col], b1 = b_hh[col + 1];
            *(float2*)(g_gh + (size_t)(r0 + q) * G3 + col) =
                make_float2(acc[j][0] + b0, acc[j][1] + b1);
            *(float2*)(g_gh + (size_t)(r0 + q + 8) * G3 + col) =
                make_float2(acc[j][2] + b0, acc[j][3] + b1);
        }
        __syncthreads();
        if (tid == 0) {
            __threadfence();
            g_flag[b] = epoch;
            __threadfence();
        }
    } else {
        // ---- gi epilogue: combine cei + b_ih into smem ----
#pragma unroll
        for (int j = 0; j < 3; j++) {
            int col = (w * 3 + j) * 8 + 2 * r;
            float bi0 = b_ih[col], bi1 = b_ih[col + 1];
#pragma unroll
            for (int s = 0; s < 2; s++) {
                int i = q + s * 8;
                float2 ce = *(const float2*)(g_cei + (size_t)(r0 + i) * G3 + col);
                G[i * GLD + col]     = acc[j][s * 2 + 0] + ce.x + bi0;
                G[i * GLD + col + 1] = acc[j][s * 2 + 1] + ce.y + bi1;
            }
        }
        __syncthreads();
        if (tid == 0) {
            while (((volatile int*)g_flag)[b] != epoch) { }
            __threadfence();
        }
        __syncthreads();

        // ---- GRU: gi from smem, gh from global (fresh L2; L1 cold) ----
#pragma unroll
        for (int rep = 0; rep < 4; rep++) {
            int eid = tid + rep * 512;          // 16*128
            int i = eid >> 7, d = eid & 127;
            int row = r0 + i;
            const float* ghr = g_gh + (size_t)row * G3;
            float rr = sigf(G[i * GLD + d]       + ghr[d]);
            float zz = sigf(G[i * GLD + 128 + d] + ghr[128 + d]);
            float nn = tanhf(G[i * GLD + 256 + d] + rr * ghr[256 + d]);
            float hold = hprev[(size_t)row * DNF + d];
            hnext[(size_t)row * DNF + d] = (1.0f - zz) * nn + zz * hold;
        }
    }
}

// ---------------------------------------------------------------------------
// k_readout: gate/out GEMMs (K=256) + sig*tanh + partial reduce + final fc.
// 64 blocks x 1024 threads. 32 warps = 2 mats x 2 k-halves x 8 frag-groups.
// ---------------------------------------------------------------------------
__global__ void __launch_bounds__(1024)
k_readout(const float* __restrict__ hfin, const float* __restrict__ h0,
          const float* __restrict__ b_gate, const float* __restrict__ b_out,
          const float* __restrict__ w_embed, const float* __restrict__ edge,
          const float* __restrict__ w_fc, const float* __restrict__ b_fc,
          float* __restrict__ out) {
    __shared__ float sAbuf[2 * 16 * SLD];   // sA0 | sA1 ; later gp | op
    __shared__ float red[16 * 32 * 9];
    __shared__ float sred[1024];
    __shared__ float sgv[128], see[128];
    __shared__ int   s_last;

    float* sA0 = sAbuf;
    float* sA1 = sAbuf + 16 * SLD;
    float* gp  = sAbuf;
    float* op  = sAbuf + 16 * SLD;

    const int tid  = threadIdx.x;
    const int lane = tid & 31;
    const int w    = tid >> 5;
    const int fg   = w & 7;
    const int mat  = (w >> 3) & 1;
    const int kh   = w >> 4;
    const int q    = lane >> 2, r = lane & 3;
    const int r0   = blockIdx.x * 16;

    {
        const float* src = (w < 16) ? hfin : h0;
        float* dst = (w < 16) ? sA0 : sA1;
        int row = r0 + (w & 15);
        float4 v = *(const float4*)(src + (size_t)row * DNF + lane * 4);
        float* d = dst + (w & 15) * SLD + lane * 4;
        d[0] = to_tf32(v.x); d[1] = to_tf32(v.y);
        d[2] = to_tf32(v.z); d[3] = to_tf32(v.w);
    }
    __syncthreads();

    const float2* bp = (const float2*)(mat ? g_woP : g_wgP);
    const float* At = kh ? sA1 : sA0;

    float acc[2][4];
#pragma unroll
    for (int j = 0; j < 2; j++)
#pragma unroll
        for (int c = 0; c < 4; c++) acc[j][c] = 0.f;

    float2 bf[2][2];
#pragma unroll
    for (int j = 0; j < 2; j++)
        bf[0][j] = bp[((kh * 16) * 16 + fg * 2 + j) * 32 + lane];

#pragma unroll
    for (int kk = 0; kk < 16; kk++) {
        const int k8 = kh * 16 + kk;
        const int cur = kk & 1, nxt = cur ^ 1;
        if (kk < 15) {
#pragma unroll
            for (int j = 0; j < 2; j++)
                bf[nxt][j] = bp[((k8 + 1) * 16 + fg * 2 + j) * 32 + lane];
        }
        const int ko = kk * 8;
        unsigned a[4];
        a[0] = __float_as_uint(At[q * SLD + ko + r]);
        a[1] = __float_as_uint(At[(q + 8) * SLD + ko + r]);
        a[2] = __float_as_uint(At[q * SLD + ko + r + 4]);
        a[3] = __float_as_uint(At[(q + 8) * SLD + ko + r + 4]);
#pragma unroll
        for (int j = 0; j < 2; j++)
            mma_tf32(acc[j], a, __float_as_uint(bf[cur][j].x),
                               __float_as_uint(bf[cur][j].y));
    }

    if (kh == 1) {
        float* rp = red + ((mat * 8 + fg) * 32 + lane) * 9;
#pragma unroll
        for (int j = 0; j < 2; j++)
#pragma unroll
            for (int c = 0; c < 4; c++) rp[j * 4 + c] = acc[j][c];
    }
    __syncthreads();
    if (kh == 0) {
        const float* rp = red + ((mat * 8 + fg) * 32 + lane) * 9;
        float* dst = mat ? op : gp;
        const float* bias = mat ? b_out : b_gate;
#pragma unroll
        for (int j = 0; j < 2; j++) {
#pragma unroll
            for (int c = 0; c < 4; c++) acc[j][c] += rp[j * 4 + c];
            int col = (fg * 2 + j) * 8 + 2 * r;
            float b0 = bias[col], b1 = bias[col + 1];
            dst[q * GB_LD + col]           = acc[j][0] + b0;
            dst[q * GB_LD + col + 1]       = acc[j][1] + b1;
            dst[(q + 8) * GB_LD + col]     = acc[j][2] + b0;
            dst[(q + 8) * GB_LD + col + 1] = acc[j][3] + b1;
        }
    }
    __syncthreads();

    {
        int grp = tid >> 7, d = tid & 127;
        float a = 0.f;
#pragma unroll
        for (int i = grp * 2; i < grp * 2 + 2; i++)
            a += sigf(gp[i * GB_LD + d]) * tanhf(op[i * GB_LD + d]);
        sred[tid] = a;
    }
    __syncthreads();
    if (tid < 128) {
        float s = 0.f;
#pragma unroll
        for (int g = 0; g < 8; g++) s += sred[g * 128 + tid];
        g_part[blockIdx.x * DNF + tid] = s;
    }
    __syncthreads();

    if (tid == 0) {
        __threadfence();
        int old = atomicAdd(&g_rc, 1);
        s_last = (old == 63) ? 1 : 0;
    }
    __syncthreads();
    if (s_last) {
        if (tid == 0) g_rc = 0;
        if (tid < 128) {
            float gv = 0.f;
            for (int b = 0; b < 64; b++) gv += g_part[b * DNF + tid];
            sgv[tid] = gv;
            float ee = 0.f;
#pragma unroll
            for (int f = 0; f < 5; f++) ee += w_embed[tid * 5 + f] * edge[f];
            see[tid] = ee;
        }
        __syncthreads();
        if (tid < 128) {
            float acc2 = b_fc[tid];
            const float* wr = w_fc + (size_t)tid * 256;
            for (int k = 0; k < 128; k++) acc2 += wr[k] * sgv[k];
            for (int k = 0; k < 128; k++) acc2 += wr[128 + k] * see[k];
            out[tid] = acc2;
        }
    }
}

// ---------------------------------------------------------------------------
extern "C" void kernel_launch(void* const* d_in, const int* in_sizes, int n_in,
                              void* d_out, int out_size) {
    const float* h_in    = (const float*)d_in[0];
    const float* e       = (const float*)d_in[1];
    const float* adj     = (const float*)d_in[2];
    const float* edge    = (const float*)d_in[3];
    const float* w_msg_h = (const float*)d_in[4];
    const float* w_msg_e = (const float*)d_in[5];
    const float* b_msg   = (const float*)d_in[6];
    const float* w_ih    = (const float*)d_in[7];
    const float* w_hh    = (const float*)d_in[8];
    const float* b_ih    = (const float*)d_in[9];
    const float* b_hh    = (const float*)d_in[10];
    const float* w_gate  = (const float*)d_in[11];
    const float* b_gate  = (const float*)d_in[12];
    const float* w_out   = (const float*)d_in[13];
    const float* b_out   = (const float*)d_in[14];
    const float* w_embed = (const float*)d_in[15];
    const float* w_fc    = (const float*)d_in[16];
    const float* b_fc    = (const float*)d_in[17];
    float* out = (float*)d_out;

    float *p_ha, *p_hb;
    cudaGetSymbolAddress((void**)&p_ha, g_ha);
    cudaGetSymbolAddress((void**)&p_hb, g_hb);

    k_setup<<<NN + 497, 256>>>(adj, e, w_msg_h, w_msg_e, w_ih, b_msg,
                               w_hh, w_gate, w_out);
    k_cei<<<64, 1024>>>();
    k_layer<<<128, 512>>>(h_in, p_ha, b_ih, b_hh, 1);
    k_layer<<<128, 512>>>(p_ha, p_hb, b_ih, b_hh, 2);
    k_layer<<<128, 512>>>(p_hb, p_ha, b_ih, b_hh, 3);
    k_layer<<<128, 512>>>(p_ha, p_hb, b_ih, b_hh, 4);
    k_readout<<<64, 1024>>>(p_hb, h_in, b_gate, b_out, w_embed, edge,
                            w_fc, b_fc, out);
}

// round 10
// speedup vs baseline: 1.1495x; 1.1495x over previous
#include <cuda_runtime.h>
#include <math.h>

#define NN   1024
#define DNF  128
#define G3   384
#define SLD  132     // A-tile smem stride: 128 k-floats + 4 pad
#define GLD  388     // gate buffer stride: 384 + 4 pad
#define GB_LD 132

// ---------------- device scratch ----------------
__device__ float g_er  [NN * DNF];
__device__ float g_cei [NN * G3];      // er @ wie^T + bvec (layer-invariant)
__device__ float g_ha  [NN * DNF];
__device__ float g_hb  [NN * DNF];
__device__ float g_wimP[16 * 48 * 64]; // paired tf32 frags (w_ih@w_msg_h), K=128,N=384
__device__ float g_wieP[16 * 48 * 64];
__device__ float g_whhP[16 * 48 * 64];
__device__ float g_wgP [32 * 16 * 64]; // w_gate, K=256, N=128
__device__ float g_woP [32 * 16 * 64];
__device__ float g_bvec[G3];
__device__ int   g_nzi [NN * NN];
__device__ float g_nzv [NN * NN];
__device__ int   g_nzc [NN];
__device__ float g_part[64 * DNF];
__device__ int   g_rc;

// ---------------- helpers ----------------
__device__ __forceinline__ float to_tf32(float x) {
    float r; asm("cvt.rna.tf32.f32 %0, %1;" : "=f"(r) : "f"(x)); return r;
}
__device__ __forceinline__ float sigf(float x) { return 1.0f / (1.0f + expf(-x)); }

__device__ __forceinline__ void mma_tf32(float* c, const unsigned* a,
                                         unsigned b0, unsigned b1) {
    asm volatile(
        "mma.sync.aligned.m16n8k8.row.col.f32.tf32.tf32.f32 "
        "{%0,%1,%2,%3}, {%4,%5,%6,%7}, {%8,%9}, {%0,%1,%2,%3};"
        : "+f"(c[0]), "+f"(c[1]), "+f"(c[2]), "+f"(c[3])
        : "r"(a[0]), "r"(a[1]), "r"(a[2]), "r"(a[3]), "r"(b0), "r"(b1));
}

// PAIRED packed index: float4 at ((kp*nfr + n8)*32 + q*4 + r) holds
// {frag(2kp,n8).x, .y, frag(2kp+1,n8).x, .y} for lane q*4+r.
__device__ __forceinline__ int pidx4(int n, int k, int nfr) {
    int n8 = n >> 3, q = n & 7, k8 = k >> 3, kk = k & 7;
    int half = kk >> 2, r = kk & 3;
    int kp = k8 >> 1, ko = k8 & 1;
    return (((kp * nfr + n8) * 32 + q * 4 + r) << 2) + ko * 2 + half;
}

// nz-list broadcast: first 64 entries register-cached per warp
__device__ __forceinline__ void get_nz(int k, int i0, int i1, float v0, float v1,
                                       const int* gip, const float* gvp,
                                       int& j, float& v) {
    if (k < 32)      { j = __shfl_sync(0xffffffffu, i0, k);      v = __shfl_sync(0xffffffffu, v0, k); }
    else if (k < 64) { j = __shfl_sync(0xffffffffu, i1, k - 32); v = __shfl_sync(0xffffffffu, v1, k - 32); }
    else             { j = gip[k]; v = gvp[k]; }
}

// strided warp gather (stride 2, start = half): partial for one row half
__device__ __forceinline__ float4 warp_gather_half(const float* __restrict__ src,
                                                   const int* gip, const float* gvp,
                                                   int cnt, int lane, int half) {
    int i0 = 0, i1 = 0; float v0 = 0.f, v1 = 0.f;
    if (lane < cnt)      { i0 = gip[lane];      v0 = gvp[lane]; }
    if (32 + lane < cnt) { i1 = gip[32 + lane]; v1 = gvp[32 + lane]; }
    float4 acc = make_float4(0.f, 0.f, 0.f, 0.f);
    int k = half;
    for (; k + 6 < cnt; k += 8) {
        int j0, j1, j2, j3; float w0, w1, w2, w3;
        get_nz(k,     i0, i1, v0, v1, gip, gvp, j0, w0);
        get_nz(k + 2, i0, i1, v0, v1, gip, gvp, j1, w1);
        get_nz(k + 4, i0, i1, v0, v1, gip, gvp, j2, w2);
        get_nz(k + 6, i0, i1, v0, v1, gip, gvp, j3, w3);
        float4 a0 = *(const float4*)(src + (size_t)j0 * DNF + lane * 4);
        float4 a1 = *(const float4*)(src + (size_t)j1 * DNF + lane * 4);
        float4 a2 = *(const float4*)(src + (size_t)j2 * DNF + lane * 4);
        float4 a3 = *(const float4*)(src + (size_t)j3 * DNF + lane * 4);
        acc.x += w0*a0.x + w1*a1.x + w2*a2.x + w3*a3.x;
        acc.y += w0*a0.y + w1*a1.y + w2*a2.y + w3*a3.y;
        acc.z += w0*a0.z + w1*a1.z + w2*a2.z + w3*a3.z;
        acc.w += w0*a0.w + w1*a1.w + w2*a2.w + w3*a3.w;
    }
    for (; k < cnt; k += 2) {
        int j; float w;
        get_nz(k, i0, i1, v0, v1, gip, gvp, j, w);
        float4 av = *(const float4*)(src + (size_t)j * DNF + lane * 4);
        acc.x += w*av.x; acc.y += w*av.y; acc.z += w*av.z; acc.w += w*av.w;
    }
    return acc;
}

// ---------------------------------------------------------------------------
// k_setup: bid<1024 — adjacency compaction + er; bid>=1024 — weight
// products (wim, wie), packing (whh, wgate, wout), bvec.   256 threads.
// ---------------------------------------------------------------------------
__global__ void __launch_bounds__(256)
k_setup(const float* __restrict__ adj, const float* __restrict__ e,
        const float* __restrict__ w_msg_h, const float* __restrict__ w_msg_e,
        const float* __restrict__ w_ih, const float* __restrict__ b_msg,
        const float* __restrict__ w_hh, const float* __restrict__ w_gate,
        const float* __restrict__ w_out) {
    const int bid = blockIdx.x;
    const int tid = threadIdx.x;

    if (bid < NN) {
        const int i    = bid;
        const int lane = tid & 31;
        const int w    = tid >> 5;

        __shared__ int   s_idx[NN];
        __shared__ float s_val[NN];
        __shared__ int   s_wcnt[8];
        __shared__ int   s_woff[8];
        __shared__ int   s_cnt;
        __shared__ float s_red[8 * DNF];

        const float* arow = adj + (size_t)i * NN;
        const int base = w * 128;

        float av[4]; unsigned mm[4];
#pragma unroll
        for (int c = 0; c < 4; c++) av[c] = arow[base + c * 32 + lane];
        int tot = 0;
#pragma unroll
        for (int c = 0; c < 4; c++) {
            mm[c] = __ballot_sync(0xffffffffu, av[c] != 0.0f);
            tot += __popc(mm[c]);
        }
        if (lane == 0) s_wcnt[w] = tot;
        __syncthreads();
        if (tid == 0) {
            int run = 0;
            for (int ww = 0; ww < 8; ww++) { s_woff[ww] = run; run += s_wcnt[ww]; }
            s_cnt = run;
        }
        __syncthreads();

        int off = s_woff[w];
        const unsigned lm = (1u << lane) - 1u;
#pragma unroll
        for (int c = 0; c < 4; c++) {
            if (av[c] != 0.0f) {
                int p = off + __popc(mm[c] & lm);
                s_idx[p] = base + c * 32 + lane;
                s_val[p] = av[c];
            }
            off += __popc(mm[c]);
        }
        __syncthreads();

        const int cnt = s_cnt;
        if (tid == 0) g_nzc[i] = cnt;
        for (int k = tid; k < cnt; k += 256) {
            g_nzi[(size_t)i * NN + k] = s_idx[k];
            g_nzv[(size_t)i * NN + k] = s_val[k];
        }

        const int q = tid & 31;
        const int g = tid >> 5;
        const float* ebase = e + (size_t)i * NN * DNF;
        float4 acc = make_float4(0.f, 0.f, 0.f, 0.f);
        for (int k = g; k < cnt; k += 8) {
            float v = s_val[k];
            float4 ev = *(const float4*)(ebase + (size_t)s_idx[k] * DNF + q * 4);
            acc.x += v * ev.x; acc.y += v * ev.y;
            acc.z += v * ev.z; acc.w += v * ev.w;
        }
        s_red[g * DNF + q * 4 + 0] = acc.x;
        s_red[g * DNF + q * 4 + 1] = acc.y;
        s_red[g * DNF + q * 4 + 2] = acc.z;
        s_red[g * DNF + q * 4 + 3] = acc.w;
        __syncthreads();
        if (tid < 128) {
            float s = 0.f;
#pragma unroll
            for (int gg = 0; gg < 8; gg++) s += s_red[gg * DNF + tid];
            g_er[(size_t)i * DNF + tid] = s;
        }
        return;
    }

    const int sid = bid - NN;
    if (sid < 384) {
        const bool is_h = (sid < 192);
        const int  lsid = is_h ? sid : sid - 192;
        const float* B = is_h ? w_msg_h : w_msg_e;
        float* P = is_h ? g_wimP : g_wieP;
        int id = lsid * 256 + tid;
        int n = id >> 7, k = id & 127;
        float acc = 0.f;
        const float* wr = w_ih + (size_t)n * DNF;
#pragma unroll 4
        for (int d = 0; d < DNF; d++) acc += wr[d] * B[(size_t)d * DNF + k];
        P[pidx4(n, k, 48)] = to_tf32(acc);
    } else if (sid < 432) {
        int b = sid - 384;
#pragma unroll
        for (int rep = 0; rep < 4; rep++) {
            int eid = b * 1024 + rep * 256 + tid;
            int n = eid >> 7, k = eid & 127;
            g_whhP[pidx4(n, k, 48)] = to_tf32(w_hh[(size_t)n * DNF + k]);
        }
    } else if (sid < 464) {
        int b = sid - 432;
#pragma unroll
        for (int rep = 0; rep < 4; rep++) {
            int eid = b * 1024 + rep * 256 + tid;
            int n = eid >> 8, k = eid & 255;
            g_wgP[pidx4(n, k, 16)] = to_tf32(w_gate[(size_t)n * 256 + k]);
        }
    } else if (sid < 496) {
        int b = sid - 464;
#pragma unroll
        for (int rep = 0; rep < 4; rep++) {
            int eid = b * 1024 + rep * 256 + tid;
            int n = eid >> 8, k = eid & 255;
            g_woP[pidx4(n, k, 16)] = to_tf32(w_out[(size_t)n * 256 + k]);
        }
    } else {
        for (int n = tid; n < G3; n += 256) {
            float acc = 0.f;
            const float* wr = w_ih + (size_t)n * DNF;
            for (int k = 0; k < DNF; k++) acc += wr[k] * b_msg[k];
            g_bvec[n] = acc;
        }
    }
}

// ---------------------------------------------------------------------------
// k_cei: cei = er @ wie^T + bvec.  64 blocks x 1024 threads.
// 32 warps = 16 n-warps x 2 k-halves (4 frag-pairs each).
// ---------------------------------------------------------------------------
__global__ void __launch_bounds__(1024)
k_cei() {
    __shared__ float sA[16 * SLD];
    __shared__ float red[16 * 32 * 13];

    const int tid  = threadIdx.x;
    const int lane = tid & 31;
    const int w    = tid >> 5;        // 32 warps
    const int nw   = w & 15;
    const int kh   = w >> 4;
    const int q    = lane >> 2, r = lane & 3;
    const int r0   = blockIdx.x * 16;

#pragma unroll
    for (int rep = 0; rep < 2; rep++) {
        int eid = tid + rep * 1024;
        int i = eid >> 7, d = eid & 127;
        sA[i * SLD + d] = to_tf32(g_er[(size_t)(r0 + i) * DNF + d]);
    }
    __syncthreads();

    float acc[3][4];
#pragma unroll
    for (int j = 0; j < 3; j++)
#pragma unroll
        for (int c = 0; c < 4; c++) acc[j][c] = 0.f;

    const float4* bp = (const float4*)g_wieP;

    float4 bf[2][3];
#pragma unroll
    for (int j = 0; j < 3; j++)
        bf[0][j] = bp[((kh * 4) * 48 + nw * 3 + j) * 32 + lane];

#pragma unroll
    for (int kk = 0; kk < 4; kk++) {
        const int kp = kh * 4 + kk;
        const int cur = kk & 1, nxt = cur ^ 1;
        if (kk < 3) {
#pragma unroll
            for (int j = 0; j < 3; j++)
                bf[nxt][j] = bp[((kp + 1) * 48 + nw * 3 + j) * 32 + lane];
        }
#pragma unroll
        for (int s8 = 0; s8 < 2; s8++) {
            const int ko = (kp * 2 + s8) * 8;
            unsigned a[4];
            a[0] = __float_as_uint(sA[q * SLD + ko + r]);
            a[1] = __float_as_uint(sA[(q + 8) * SLD + ko + r]);
            a[2] = __float_as_uint(sA[q * SLD + ko + r + 4]);
            a[3] = __float_as_uint(sA[(q + 8) * SLD + ko + r + 4]);
#pragma unroll
            for (int j = 0; j < 3; j++) {
                unsigned b0 = s8 ? __float_as_uint(bf[cur][j].z)
                                 : __float_as_uint(bf[cur][j].x);
                unsigned b1 = s8 ? __float_as_uint(bf[cur][j].w)
                                 : __float_as_uint(bf[cur][j].y);
                mma_tf32(acc[j], a, b0, b1);
            }
        }
    }

    if (kh == 1) {
        float* rp = red + (nw * 32 + lane) * 13;
#pragma unroll
        for (int j = 0; j < 3; j++)
#pragma unroll
            for (int c = 0; c < 4; c++) rp[j * 4 + c] = acc[j][c];
    }
    __syncthreads();
    if (kh == 0) {
        const float* rp = red + (nw * 32 + lane) * 13;
#pragma unroll
        for (int j = 0; j < 3; j++) {
#pragma unroll
            for (int c = 0; c < 4; c++) acc[j][c] += rp[j * 4 + c];
            int col = (nw * 3 + j) * 8 + 2 * r;
            float bv0 = g_bvec[col], bv1 = g_bvec[col + 1];
            *(float2*)(g_cei + (size_t)(r0 + q) * G3 + col) =
                make_float2(acc[j][0] + bv0, acc[j][1] + bv1);
            *(float2*)(g_cei + (size_t)(r0 + q + 8) * G3 + col) =
                make_float2(acc[j][2] + bv0, acc[j][3] + bv1);
        }
    }
}

// ---------------------------------------------------------------------------
// k_layer: fused spmv + dual TF32 GEMM + GRU for 16 rows. 64 blocks x 1024 thr.
// 32 warps = 2 matrices x 16 n-warps; paired-k8 float4 weight loads.
// ---------------------------------------------------------------------------
__global__ void __launch_bounds__(1024)
k_layer(const float* __restrict__ hprev, float* __restrict__ hnext,
        const float* __restrict__ b_ih, const float* __restrict__ b_hh) {
    __shared__ float sAbuf[2 * 16 * SLD];   // sh_t | hh_t ; sh_t later = gbi
    __shared__ float G[16 * GLD];           // first used as ph[32][32] float4

    float*  sh_t = sAbuf;
    float*  hh_t = sAbuf + 16 * SLD;
    float*  gbi  = sAbuf;                   // alias (valid after MMA sync)
    float4* ph   = (float4*)G;

    const int tid  = threadIdx.x;
    const int lane = tid & 31;
    const int w    = tid >> 5;              // 32 warps
    const int q    = lane >> 2, r = lane & 3;
    const int r0   = blockIdx.x * 16;

    // ---- phase 1a: strided gather halves (2 warps per row) ----
    {
        const int row  = r0 + (w & 15);
        const int half = w >> 4;
        const int cnt  = g_nzc[row];
        const int*   gip = g_nzi + (size_t)row * NN;
        const float* gvp = g_nzv + (size_t)row * NN;
        ph[w * 32 + lane] = warp_gather_half(hprev, gip, gvp, cnt, lane, half);
    }
    __syncthreads();

    // ---- phase 1b: combine halves -> sh_t ; stage h -> hh_t ----
    if (w < 16) {
        float4 a = ph[w * 32 + lane];
        float4 b = ph[(w + 16) * 32 + lane];
        float* d = sh_t + w * SLD + lane * 4;
        d[0] = to_tf32(a.x + b.x); d[1] = to_tf32(a.y + b.y);
        d[2] = to_tf32(a.z + b.z); d[3] = to_tf32(a.w + b.w);
    } else {
        int row = r0 + (w - 16);
        float4 hv = *(const float4*)(hprev + (size_t)row * DNF + lane * 4);
        float* dh = hh_t + (w - 16) * SLD + lane * 4;
        dh[0] = to_tf32(hv.x); dh[1] = to_tf32(hv.y);
        dh[2] = to_tf32(hv.z); dh[3] = to_tf32(hv.w);
    }
    __syncthreads();

    // ---- phase 2: MMA (mat 0: gi = sh@wim^T ; mat 1: gh = h@whh^T) ----
    const int mat = w >> 4;
    const int nw  = w & 15;
    const float*  At = mat ? hh_t : sh_t;
    const float4* bp = (const float4*)(mat ? g_whhP : g_wimP);

    float acc[3][4];
#pragma unroll
    for (int j = 0; j < 3; j++)
#pragma unroll
        for (int c = 0; c < 4; c++) acc[j][c] = 0.f;

    float4 bf[2][3];
#pragma unroll
    for (int j = 0; j < 3; j++)
        bf[0][j] = bp[(0 * 48 + nw * 3 + j) * 32 + lane];

#pragma unroll
    for (int kp = 0; kp < 8; kp++) {
        const int cur = kp & 1, nxt = cur ^ 1;
        if (kp < 7) {
#pragma unroll
            for (int j = 0; j < 3; j++)
                bf[nxt][j] = bp[((kp + 1) * 48 + nw * 3 + j) * 32 + lane];
        }
#pragma unroll
        for (int s8 = 0; s8 < 2; s8++) {
            const int ko = (kp * 2 + s8) * 8;
            unsigned a[4];
            a[0] = __float_as_uint(At[q * SLD + ko + r]);
            a[1] = __float_as_uint(At[(q + 8) * SLD + ko + r]);
            a[2] = __float_as_uint(At[q * SLD + ko + r + 4]);
            a[3] = __float_as_uint(At[(q + 8) * SLD + ko + r + 4]);
#pragma unroll
            for (int j = 0; j < 3; j++) {
                unsigned b0 = s8 ? __float_as_uint(bf[cur][j].z)
                                 : __float_as_uint(bf[cur][j].x);
                unsigned b1 = s8 ? __float_as_uint(bf[cur][j].w)
                                 : __float_as_uint(bf[cur][j].y);
                mma_tf32(acc[j], a, b0, b1);
            }
        }
    }

    // gh warps: write gh + b_hh into G (ph already consumed)
    if (mat == 1) {
#pragma unroll
        for (int j = 0; j < 3; j++) {
            int col = (nw * 3 + j) * 8 + 2 * r;
            float b0 = b_hh[col], b1 = b_hh[col + 1];
            G[q * GLD + col]           = acc[j][0] + b0;
            G[q * GLD + col + 1]       = acc[j][1] + b1;
            G[(q + 8) * GLD + col]     = acc[j][2] + b0;
            G[(q + 8) * GLD + col + 1] = acc[j][3] + b1;
        }
    }
    __syncthreads();

    // gi warps: combine with cei + b_ih
    if (mat == 0) {
#pragma unroll
        for (int j = 0; j < 3; j++) {
            int col = (nw * 3 + j) * 8 + 2 * r;
            float bi0 = b_ih[col], bi1 = b_ih[col + 1];
#pragma unroll
            for (int s = 0; s < 2; s++) {
                int i = q + s * 8;
                int row = r0 + i;
                float2 ce = *(const float2*)(g_cei + (size_t)row * G3 + col);
                float gi0 = acc[j][s * 2 + 0] + ce.x + bi0;
                float gi1 = acc[j][s * 2 + 1] + ce.y + bi1;
                if (col < 256) {
                    G[i * GLD + col]     += gi0;
                    G[i * GLD + col + 1] += gi1;
                } else {
                    gbi[i * GB_LD + (col - 256)]     = gi0;
                    gbi[i * GB_LD + (col - 256) + 1] = gi1;
                }
            }
        }
    }
    __syncthreads();

    // ---- GRU ----
#pragma unroll
    for (int rep = 0; rep < 2; rep++) {
        int eid = tid + rep * 1024;             // 16*128
        int i = eid >> 7, d = eid & 127;
        int row = r0 + i;
        float rr = sigf(G[i * GLD + d]);
        float zz = sigf(G[i * GLD + 128 + d]);
        float nn = tanhf(gbi[i * GB_LD + d] + rr * G[i * GLD + 256 + d]);
        float hold = hprev[(size_t)row * DNF + d];
        hnext[(size_t)row * DNF + d] = (1.0f - zz) * nn + zz * hold;
    }
}

// ---------------------------------------------------------------------------
// k_readout: gate/out GEMMs (K=256) + sig*tanh + partial reduce + final fc.
// 64 blocks x 1024 threads. 32 warps = 2 mats x 2 k-halves x 8 frag-groups.
// ---------------------------------------------------------------------------
__global__ void __launch_bounds__(1024)
k_readout(const float* __restrict__ hfin, const float* __restrict__ h0,
          const float* __restrict__ b_gate, const float* __restrict__ b_out,
          const float* __restrict__ w_embed, const float* __restrict__ edge,
          const float* __restrict__ w_fc, const float* __restrict__ b_fc,
          float* __restrict__ out) {
    __shared__ float sAbuf[2 * 16 * SLD];   // sA0 | sA1 ; later gp | op
    __shared__ float red[16 * 32 * 9];
    __shared__ float sred[1024];
    __shared__ float sgv[128], see[128];
    __shared__ int   s_last;

    float* sA0 = sAbuf;
    float* sA1 = sAbuf + 16 * SLD;
    float* gp  = sAbuf;
    float* op  = sAbuf + 16 * SLD;

    const int tid  = threadIdx.x;
    const int lane = tid & 31;
    const int w    = tid >> 5;              // 32 warps
    const int fg   = w & 7;
    const int mat  = (w >> 3) & 1;
    const int kh   = w >> 4;
    const int q    = lane >> 2, r = lane & 3;
    const int r0   = blockIdx.x * 16;

    {
        const float* src = (w < 16) ? hfin : h0;
        float* dst = (w < 16) ? sA0 : sA1;
        int row = r0 + (w & 15);
        float4 v = *(const float4*)(src + (size_t)row * DNF + lane * 4);
        float* d = dst + (w & 15) * SLD + lane * 4;
        d[0] = to_tf32(v.x); d[1] = to_tf32(v.y);
        d[2] = to_tf32(v.z); d[3] = to_tf32(v.w);
    }
    __syncthreads();

    const float4* bp = (const float4*)(mat ? g_woP : g_wgP);
    const float* At = kh ? sA1 : sA0;

    float acc[2][4];
#pragma unroll
    for (int j = 0; j < 2; j++)
#pragma unroll
        for (int c = 0; c < 4; c++) acc[j][c] = 0.f;

    float4 bf[2][2];
#pragma unroll
    for (int j = 0; j < 2; j++)
        bf[0][j] = bp[((kh * 8) * 16 + fg * 2 + j) * 32 + lane];

#pragma unroll
    for (int kk = 0; kk < 8; kk++) {
        const int kp = kh * 8 + kk;
        const int cur = kk & 1, nxt = cur ^ 1;
        if (kk < 7) {
#pragma unroll
            for (int j = 0; j < 2; j++)
                bf[nxt][j] = bp[((kp + 1) * 16 + fg * 2 + j) * 32 + lane];
        }
#pragma unroll
        for (int s8 = 0; s8 < 2; s8++) {
            const int ko = (kk * 2 + s8) * 8;
            unsigned a[4];
            a[0] = __float_as_uint(At[q * SLD + ko + r]);
            a[1] = __float_as_uint(At[(q + 8) * SLD + ko + r]);
            a[2] = __float_as_uint(At[q * SLD + ko + r + 4]);
            a[3] = __float_as_uint(At[(q + 8) * SLD + ko + r + 4]);
#pragma unroll
            for (int j = 0; j < 2; j++) {
                unsigned b0 = s8 ? __float_as_uint(bf[cur][j].z)
                                 : __float_as_uint(bf[cur][j].x);
                unsigned b1 = s8 ? __float_as_uint(bf[cur][j].w)
                                 : __float_as_uint(bf[cur][j].y);
                mma_tf32(acc[j], a, b0, b1);
            }
        }
    }

    if (kh == 1) {
        float* rp = red + ((mat * 8 + fg) * 32 + lane) * 9;
#pragma unroll
        for (int j = 0; j < 2; j++)
#pragma unroll
            for (int c = 0; c < 4; c++) rp[j * 4 + c] = acc[j][c];
    }
    __syncthreads();
    if (kh == 0) {
        const float* rp = red + ((mat * 8 + fg) * 32 + lane) * 9;
        float* dst = mat ? op : gp;
        const float* bias = mat ? b_out : b_gate;
#pragma unroll
        for (int j = 0; j < 2; j++) {
#pragma unroll
            for (int c = 0; c < 4; c++) acc[j][c] += rp[j * 4 + c];
            int col = (fg * 2 + j) * 8 + 2 * r;
            float b0 = bias[col], b1 = bias[col + 1];
            dst[q * GB_LD + col]           = acc[j][0] + b0;
            dst[q * GB_LD + col + 1]       = acc[j][1] + b1;
            dst[(q + 8) * GB_LD + col]     = acc[j][2] + b0;
            dst[(q + 8) * GB_LD + col + 1] = acc[j][3] + b1;
        }
    }
    __syncthreads();

    {
        int grp = tid >> 7, d = tid & 127;
        float a = 0.f;
#pragma unroll
        for (int i = grp * 2; i < grp * 2 + 2; i++)
            a += sigf(gp[i * GB_LD + d]) * tanhf(op[i * GB_LD + d]);
        sred[tid] = a;
    }
    __syncthreads();
    if (tid < 128) {
        float s = 0.f;
#pragma unroll
        for (int g = 0; g < 8; g++) s += sred[g * 128 + tid];
        g_part[blockIdx.x * DNF + tid] = s;
    }
    __syncthreads();

    if (tid == 0) {
        __threadfence();
        int old = atomicAdd(&g_rc, 1);
        s_last = (old == 63) ? 1 : 0;
    }
    __syncthreads();
    if (s_last) {
        if (tid == 0) g_rc = 0;
        if (tid < 128) {
            float gv = 0.f;
            for (int b = 0; b < 64; b++) gv += g_part[b * DNF + tid];
            sgv[tid] = gv;
            float ee = 0.f;
#pragma unroll
            for (int f = 0; f < 5; f++) ee += w_embed[tid * 5 + f] * edge[f];
            see[tid] = ee;
        }
        __syncthreads();
        if (tid < 128) {
            float acc2 = b_fc[tid];
            const float* wr = w_fc + (size_t)tid * 256;
            for (int k = 0; k < 128; k++) acc2 += wr[k] * sgv[k];
            for (int k = 0; k < 128; k++) acc2 += wr[128 + k] * see[k];
            out[tid] = acc2;
        }
    }
}

// ---------------------------------------------------------------------------
extern "C" void kernel_launch(void* const* d_in, const int* in_sizes, int n_in,
                              void* d_out, int out_size) {
    const float* h_in    = (const float*)d_in[0];
    const float* e       = (const float*)d_in[1];
    const float* adj     = (const float*)d_in[2];
    const float* edge    = (const float*)d_in[3];
    const float* w_msg_h = (const float*)d_in[4];
    const float* w_msg_e = (const float*)d_in[5];
    const float* b_msg   = (const float*)d_in[6];
    const float* w_ih    = (const float*)d_in[7];
    const float* w_hh    = (const float*)d_in[8];
    const float* b_ih    = (const float*)d_in[9];
    const float* b_hh    = (const float*)d_in[10];
    const float* w_gate  = (const float*)d_in[11];
    const float* b_gate  = (const float*)d_in[12];
    const float* w_out   = (const float*)d_in[13];
    const float* b_out   = (const float*)d_in[14];
    const float* w_embed = (const float*)d_in[15];
    const float* w_fc    = (const float*)d_in[16];
    const float* b_fc    = (const float*)d_in[17];
    float* out = (float*)d_out;

    float *p_ha, *p_hb;
    cudaGetSymbolAddress((void**)&p_ha, g_ha);
    cudaGetSymbolAddress((void**)&p_hb, g_hb);

    k_setup<<<NN + 497, 256>>>(adj, e, w_msg_h, w_msg_e, w_ih, b_msg,
                               w_hh, w_gate, w_out);
    k_cei<<<64, 1024>>>();
    k_layer<<<64, 1024>>>(h_in, p_ha, b_ih, b_hh);
    k_layer<<<64, 1024>>>(p_ha, p_hb, b_ih, b_hh);
    k_layer<<<64, 1024>>>(p_hb, p_ha, b_ih, b_hh);
    k_layer<<<64, 1024>>>(p_ha, p_hb, b_ih, b_hh);
    k_readout<<<64, 1024>>>(p_hb, h_in, b_gate, b_out, w_embed, edge,
                            w_fc, b_fc, out);
}

// round 11
// speedup vs baseline: 1.2448x; 1.0829x over previous
#include <cuda_runtime.h>
#include <cuda_fp16.h>
#include <math.h>

#define NN   1024
#define DNF  128
#define G3   384
#define ALD  136     // fp16 A-tile stride in halves (68 words: (4q+r) conflict-free)
#define GLD  388     // gate buffer stride: 384 + 4 pad
#define GB_LD 132

// ---------------- device scratch ----------------
__device__ float g_er  [NN * DNF];
__device__ float g_cei [NN * G3];       // er @ wie^T + bvec (layer-invariant)
__device__ float g_ha  [NN * DNF];
__device__ float g_hb  [NN * DNF];
__device__ __half g_wimH[G3 * DNF];     // fp16 frag-packed (w_ih@w_msg_h)
__device__ __half g_wieH[G3 * DNF];
__device__ __half g_whhH[G3 * DNF];
__device__ __half g_wgH [DNF * 256];
__device__ __half g_woH [DNF * 256];
__device__ float g_bvec[G3];
__device__ int   g_nzi [NN * NN];
__device__ float g_nzv [NN * NN];
__device__ int   g_nzc [NN];
__device__ float g_part[64 * DNF];
__device__ int   g_rc;

// ---------------- helpers ----------------
__device__ __forceinline__ float sigf(float x) { return 1.0f / (1.0f + expf(-x)); }

__device__ __forceinline__ void mma_f16(float* c,
                                        unsigned a0, unsigned a1,
                                        unsigned a2, unsigned a3,
                                        unsigned b0, unsigned b1) {
    asm volatile(
        "mma.sync.aligned.m16n8k16.row.col.f32.f16.f16.f32 "
        "{%0,%1,%2,%3}, {%4,%5,%6,%7}, {%8,%9}, {%0,%1,%2,%3};"
        : "+f"(c[0]), "+f"(c[1]), "+f"(c[2]), "+f"(c[3])
        : "r"(a0), "r"(a1), "r"(a2), "r"(a3), "r"(b0), "r"(b1));
}

// fp16 frag-packed index for W[N][K] (k-major rows).
// uint4 at ((u*nfr + f)*32 + q*4 + r) holds, for k16 steps t=2u,2u+1:
//   word(tk*2+half) = {W[f*8+q][16t+8*half+2r], W[...][+1]} as fp16x2.
__device__ __forceinline__ int hidx(int n, int k, int nfr) {
    int f = n >> 3, q = n & 7;
    int t = k >> 4, kk = k & 15;
    int half = kk >> 3;
    int r = (kk & 7) >> 1;
    int lo = kk & 1;
    int u = t >> 1, tk = t & 1;
    return ((((u * nfr + f) * 32 + q * 4 + r) * 4) + tk * 2 + half) * 2 + lo;
}

// nz-list broadcast: first 64 entries register-cached per warp
__device__ __forceinline__ void get_nz(int k, int i0, int i1, float v0, float v1,
                                       const int* gip, const float* gvp,
                                       int& j, float& v) {
    if (k < 32)      { j = __shfl_sync(0xffffffffu, i0, k);      v = __shfl_sync(0xffffffffu, v0, k); }
    else if (k < 64) { j = __shfl_sync(0xffffffffu, i1, k - 32); v = __shfl_sync(0xffffffffu, v1, k - 32); }
    else             { j = gip[k]; v = gvp[k]; }
}

// strided warp gather (stride 2, start = half): partial for one row half
__device__ __forceinline__ float4 warp_gather_half(const float* __restrict__ src,
                                                   const int* gip, const float* gvp,
                                                   int cnt, int lane, int half) {
    int i0 = 0, i1 = 0; float v0 = 0.f, v1 = 0.f;
    if (lane < cnt)      { i0 = gip[lane];      v0 = gvp[lane]; }
    if (32 + lane < cnt) { i1 = gip[32 + lane]; v1 = gvp[32 + lane]; }
    float4 acc = make_float4(0.f, 0.f, 0.f, 0.f);
    int k = half;
    for (; k + 6 < cnt; k += 8) {
        int j0, j1, j2, j3; float w0, w1, w2, w3;
        get_nz(k,     i0, i1, v0, v1, gip, gvp, j0, w0);
        get_nz(k + 2, i0, i1, v0, v1, gip, gvp, j1, w1);
        get_nz(k + 4, i0, i1, v0, v1, gip, gvp, j2, w2);
        get_nz(k + 6, i0, i1, v0, v1, gip, gvp, j3, w3);
        float4 a0 = *(const float4*)(src + (size_t)j0 * DNF + lane * 4);
        float4 a1 = *(const float4*)(src + (size_t)j1 * DNF + lane * 4);
        float4 a2 = *(const float4*)(src + (size_t)j2 * DNF + lane * 4);
        float4 a3 = *(const float4*)(src + (size_t)j3 * DNF + lane * 4);
        acc.x += w0*a0.x + w1*a1.x + w2*a2.x + w3*a3.x;
        acc.y += w0*a0.y + w1*a1.y + w2*a2.y + w3*a3.y;
        acc.z += w0*a0.z + w1*a1.z + w2*a2.z + w3*a3.z;
        acc.w += w0*a0.w + w1*a1.w + w2*a2.w + w3*a3.w;
    }
    for (; k < cnt; k += 2) {
        int j; float w;
        get_nz(k, i0, i1, v0, v1, gip, gvp, j, w);
        float4 av = *(const float4*)(src + (size_t)j * DNF + lane * 4);
        acc.x += w*av.x; acc.y += w*av.y; acc.z += w*av.z; acc.w += w*av.w;
    }
    return acc;
}

// ---------------------------------------------------------------------------
// k_setup: bid<1024 — adjacency compaction + er; bid>=1024 — weight
// products (wim, wie), fp16 packing (whh, wgate, wout), bvec.   256 threads.
// ---------------------------------------------------------------------------
__global__ void __launch_bounds__(256)
k_setup(const float* __restrict__ adj, const float* __restrict__ e,
        const float* __restrict__ w_msg_h, const float* __restrict__ w_msg_e,
        const float* __restrict__ w_ih, const float* __restrict__ b_msg,
        const float* __restrict__ w_hh, const float* __restrict__ w_gate,
        const float* __restrict__ w_out) {
    const int bid = blockIdx.x;
    const int tid = threadIdx.x;

    if (bid < NN) {
        const int i    = bid;
        const int lane = tid & 31;
        const int w    = tid >> 5;

        __shared__ int   s_idx[NN];
        __shared__ float s_val[NN];
        __shared__ int   s_wcnt[8];
        __shared__ int   s_woff[8];
        __shared__ int   s_cnt;
        __shared__ float s_red[8 * DNF];

        const float* arow = adj + (size_t)i * NN;
        const int base = w * 128;

        float av[4]; unsigned mm[4];
#pragma unroll
        for (int c = 0; c < 4; c++) av[c] = arow[base + c * 32 + lane];
        int tot = 0;
#pragma unroll
        for (int c = 0; c < 4; c++) {
            mm[c] = __ballot_sync(0xffffffffu, av[c] != 0.0f);
            tot += __popc(mm[c]);
        }
        if (lane == 0) s_wcnt[w] = tot;
        __syncthreads();
        if (tid == 0) {
            int run = 0;
            for (int ww = 0; ww < 8; ww++) { s_woff[ww] = run; run += s_wcnt[ww]; }
            s_cnt = run;
        }
        __syncthreads();

        int off = s_woff[w];
        const unsigned lm = (1u << lane) - 1u;
#pragma unroll
        for (int c = 0; c < 4; c++) {
            if (av[c] != 0.0f) {
                int p = off + __popc(mm[c] & lm);
                s_idx[p] = base + c * 32 + lane;
                s_val[p] = av[c];
            }
            off += __popc(mm[c]);
        }
        __syncthreads();

        const int cnt = s_cnt;
        if (tid == 0) g_nzc[i] = cnt;
        for (int k = tid; k < cnt; k += 256) {
            g_nzi[(size_t)i * NN + k] = s_idx[k];
            g_nzv[(size_t)i * NN + k] = s_val[k];
        }

        const int q = tid & 31;
        const int g = tid >> 5;
        const float* ebase = e + (size_t)i * NN * DNF;
        float4 acc = make_float4(0.f, 0.f, 0.f, 0.f);
        for (int k = g; k < cnt; k += 8) {
            float v = s_val[k];
            float4 ev = *(const float4*)(ebase + (size_t)s_idx[k] * DNF + q * 4);
            acc.x += v * ev.x; acc.y += v * ev.y;
            acc.z += v * ev.z; acc.w += v * ev.w;
        }
        s_red[g * DNF + q * 4 + 0] = acc.x;
        s_red[g * DNF + q * 4 + 1] = acc.y;
        s_red[g * DNF + q * 4 + 2] = acc.z;
        s_red[g * DNF + q * 4 + 3] = acc.w;
        __syncthreads();
        if (tid < 128) {
            float s = 0.f;
#pragma unroll
            for (int gg = 0; gg < 8; gg++) s += s_red[gg * DNF + tid];
            g_er[(size_t)i * DNF + tid] = s;
        }
        return;
    }

    const int sid = bid - NN;
    if (sid < 384) {
        const bool is_h = (sid < 192);
        const int  lsid = is_h ? sid : sid - 192;
        const float* B = is_h ? w_msg_h : w_msg_e;
        __half* P = is_h ? g_wimH : g_wieH;
        int id = lsid * 256 + tid;
        int n = id >> 7, k = id & 127;
        float acc = 0.f;
        const float* wr = w_ih + (size_t)n * DNF;
#pragma unroll 4
        for (int d = 0; d < DNF; d++) acc += wr[d] * B[(size_t)d * DNF + k];
        P[hidx(n, k, 48)] = __float2half_rn(acc);
    } else if (sid < 432) {
        int b = sid - 384;
#pragma unroll
        for (int rep = 0; rep < 4; rep++) {
            int eid = b * 1024 + rep * 256 + tid;
            int n = eid >> 7, k = eid & 127;
            g_whhH[hidx(n, k, 48)] = __float2half_rn(w_hh[(size_t)n * DNF + k]);
        }
    } else if (sid < 464) {
        int b = sid - 432;
#pragma unroll
        for (int rep = 0; rep < 4; rep++) {
            int eid = b * 1024 + rep * 256 + tid;
            int n = eid >> 8, k = eid & 255;
            g_wgH[hidx(n, k, 16)] = __float2half_rn(w_gate[(size_t)n * 256 + k]);
        }
    } else if (sid < 496) {
        int b = sid - 464;
#pragma unroll
        for (int rep = 0; rep < 4; rep++) {
            int eid = b * 1024 + rep * 256 + tid;
            int n = eid >> 8, k = eid & 255;
            g_woH[hidx(n, k, 16)] = __float2half_rn(w_out[(size_t)n * 256 + k]);
        }
    } else {
        for (int n = tid; n < G3; n += 256) {
            float acc = 0.f;
            const float* wr = w_ih + (size_t)n * DNF;
            for (int k = 0; k < DNF; k++) acc += wr[k] * b_msg[k];
            g_bvec[n] = acc;
        }
    }
}

// ---------------------------------------------------------------------------
// k_cei: cei = er @ wie^T + bvec.  64 blocks x 1024 threads, fp16 MMA.
// 32 warps = 16 n-warps x 2 k-halves (2 uint4 steps each).
// ---------------------------------------------------------------------------
__global__ void __launch_bounds__(1024)
k_cei() {
    __shared__ __align__(16) __half sA[16 * ALD];
    __shared__ float red[16 * 32 * 13];

    const int tid  = threadIdx.x;
    const int lane = tid & 31;
    const int w    = tid >> 5;        // 32 warps
    const int nw   = w & 15;
    const int kh   = w >> 4;
    const int q    = lane >> 2, r = lane & 3;
    const int r0   = blockIdx.x * 16;

#pragma unroll
    for (int rep = 0; rep < 2; rep++) {
        int eid = tid + rep * 1024;
        int i = eid >> 7, d = eid & 127;
        sA[i * ALD + d] = __float2half_rn(g_er[(size_t)(r0 + i) * DNF + d]);
    }
    __syncthreads();

    const unsigned* Aw = (const unsigned*)sA;    // 68-word rows

    float acc[3][4];
#pragma unroll
    for (int j = 0; j < 3; j++)
#pragma unroll
        for (int c = 0; c < 4; c++) acc[j][c] = 0.f;

    const uint4* bp = (const uint4*)g_wieH;

    uint4 bf[2][3];
#pragma unroll
    for (int j = 0; j < 3; j++)
        bf[0][j] = bp[((kh * 2) * 48 + nw * 3 + j) * 32 + lane];

#pragma unroll
    for (int kk = 0; kk < 2; kk++) {
        const int u = kh * 2 + kk;
        const int cur = kk & 1, nxt = cur ^ 1;
        if (kk < 1) {
#pragma unroll
            for (int j = 0; j < 3; j++)
                bf[nxt][j] = bp[((u + 1) * 48 + nw * 3 + j) * 32 + lane];
        }
#pragma unroll
        for (int tk = 0; tk < 2; tk++) {
            const int off = (u * 2 + tk) * 8;
            unsigned a0 = Aw[q * 68 + off + r];
            unsigned a1 = Aw[(q + 8) * 68 + off + r];
            unsigned a2 = Aw[q * 68 + off + 4 + r];
            unsigned a3 = Aw[(q + 8) * 68 + off + 4 + r];
#pragma unroll
            for (int j = 0; j < 3; j++) {
                unsigned b0 = tk ? bf[cur][j].z : bf[cur][j].x;
                unsigned b1 = tk ? bf[cur][j].w : bf[cur][j].y;
                mma_f16(acc[j], a0, a1, a2, a3, b0, b1);
            }
        }
    }

    if (kh == 1) {
        float* rp = red + (nw * 32 + lane) * 13;
#pragma unroll
        for (int j = 0; j < 3; j++)
#pragma unroll
            for (int c = 0; c < 4; c++) rp[j * 4 + c] = acc[j][c];
    }
    __syncthreads();
    if (kh == 0) {
        const float* rp = red + (nw * 32 + lane) * 13;
#pragma unroll
        for (int j = 0; j < 3; j++) {
#pragma unroll
            for (int c = 0; c < 4; c++) acc[j][c] += rp[j * 4 + c];
            int col = (nw * 3 + j) * 8 + 2 * r;
            float bv0 = g_bvec[col], bv1 = g_bvec[col + 1];
            *(float2*)(g_cei + (size_t)(r0 + q) * G3 + col) =
                make_float2(acc[j][0] + bv0, acc[j][1] + bv1);
            *(float2*)(g_cei + (size_t)(r0 + q + 8) * G3 + col) =
                make_float2(acc[j][2] + bv0, acc[j][3] + bv1);
        }
    }
}

// ---------------------------------------------------------------------------
// k_layer: fused spmv + dual fp16 GEMM + GRU for 16 rows. 64 blocks x 1024 thr.
// ---------------------------------------------------------------------------
__global__ void __launch_bounds__(1024)
k_layer(const float* __restrict__ hprev, float* __restrict__ hnext,
        const float* __restrict__ b_ih, const float* __restrict__ b_hh) {
    __shared__ __align__(16) __half sAh[2 * 16 * ALD];  // sh | hh ; later gbi
    __shared__ __align__(16) float G[16 * GLD];         // first: ph[32][32] f4

    __half* shA = sAh;
    __half* hhA = sAh + 16 * ALD;
    float*  gbi = (float*)sAh;              // alias: 8448B <= 8704B
    float4* ph  = (float4*)G;

    const int tid  = threadIdx.x;
    const int lane = tid & 31;
    const int w    = tid >> 5;              // 32 warps
    const int q    = lane >> 2, r = lane & 3;
    const int r0   = blockIdx.x * 16;

    // ---- phase 1a: strided gather halves (2 warps per row) ----
    {
        const int row  = r0 + (w & 15);
        const int half = w >> 4;
        const int cnt  = g_nzc[row];
        const int*   gip = g_nzi + (size_t)row * NN;
        const float* gvp = g_nzv + (size_t)row * NN;
        ph[w * 32 + lane] = warp_gather_half(hprev, gip, gvp, cnt, lane, half);
    }
    __syncthreads();

    // ---- phase 1b: combine halves -> shA (fp16) ; stage h -> hhA (fp16) ----
    if (w < 16) {
        float4 a = ph[w * 32 + lane];
        float4 b = ph[(w + 16) * 32 + lane];
        __half2* rp = (__half2*)(shA + w * ALD);
        rp[lane * 2]     = __floats2half2_rn(a.x + b.x, a.y + b.y);
        rp[lane * 2 + 1] = __floats2half2_rn(a.z + b.z, a.w + b.w);
    } else {
        int row = r0 + (w - 16);
        float4 hv = *(const float4*)(hprev + (size_t)row * DNF + lane * 4);
        __half2* rp = (__half2*)(hhA + (w - 16) * ALD);
        rp[lane * 2]     = __floats2half2_rn(hv.x, hv.y);
        rp[lane * 2 + 1] = __floats2half2_rn(hv.z, hv.w);
    }
    __syncthreads();

    // ---- phase 2: MMA (mat 0: gi = sh@wim^T ; mat 1: gh = h@whh^T) ----
    const int mat = w >> 4;
    const int nw  = w & 15;
    const unsigned* Aw = (const unsigned*)(mat ? hhA : shA);
    const uint4* bp = (const uint4*)(mat ? g_whhH : g_wimH);

    float acc[3][4];
#pragma unroll
    for (int j = 0; j < 3; j++)
#pragma unroll
        for (int c = 0; c < 4; c++) acc[j][c] = 0.f;

    uint4 bf[2][3];
#pragma unroll
    for (int j = 0; j < 3; j++)
        bf[0][j] = bp[(0 * 48 + nw * 3 + j) * 32 + lane];

#pragma unroll
    for (int u = 0; u < 4; u++) {
        const int cur = u & 1, nxt = cur ^ 1;
        if (u < 3) {
#pragma unroll
            for (int j = 0; j < 3; j++)
                bf[nxt][j] = bp[((u + 1) * 48 + nw * 3 + j) * 32 + lane];
        }
#pragma unroll
        for (int tk = 0; tk < 2; tk++) {
            const int off = (u * 2 + tk) * 8;
            unsigned a0 = Aw[q * 68 + off + r];
            unsigned a1 = Aw[(q + 8) * 68 + off + r];
            unsigned a2 = Aw[q * 68 + off + 4 + r];
            unsigned a3 = Aw[(q + 8) * 68 + off + 4 + r];
#pragma unroll
            for (int j = 0; j < 3; j++) {
                unsigned b0 = tk ? bf[cur][j].z : bf[cur][j].x;
                unsigned b1 = tk ? bf[cur][j].w : bf[cur][j].y;
                mma_f16(acc[j], a0, a1, a2, a3, b0, b1);
            }
        }
    }

    // gh warps: write gh + b_hh into G (ph already consumed)
    if (mat == 1) {
#pragma unroll
        for (int j = 0; j < 3; j++) {
            int col = (nw * 3 + j) * 8 + 2 * r;
            float b0 = b_hh[col], b1 = b_hh[col + 1];
            G[q * GLD + col]           = acc[j][0] + b0;
            G[q * GLD + col + 1]       = acc[j][1] + b1;
            G[(q + 8) * GLD + col]     = acc[j][2] + b0;
            G[(q + 8) * GLD + col + 1] = acc[j][3] + b1;
        }
    }
    __syncthreads();

    // gi warps: combine with cei + b_ih
    if (mat == 0) {
#pragma unroll
        for (int j = 0; j < 3; j++) {
            int col = (nw * 3 + j) * 8 + 2 * r;
            float bi0 = b_ih[col], bi1 = b_ih[col + 1];
#pragma unroll
            for (int s = 0; s < 2; s++) {
                int i = q + s * 8;
                int row = r0 + i;
                float2 ce = *(const float2*)(g_cei + (size_t)row * G3 + col);
                float gi0 = acc[j][s * 2 + 0] + ce.x + bi0;
                float gi1 = acc[j][s * 2 + 1] + ce.y + bi1;
                if (col < 256) {
                    G[i * GLD + col]     += gi0;
                    G[i * GLD + col + 1] += gi1;
                } else {
                    gbi[i * GB_LD + (col - 256)]     = gi0;
                    gbi[i * GB_LD + (col - 256) + 1] = gi1;
                }
            }
        }
    }
    __syncthreads();

    // ---- GRU ----
#pragma unroll
    for (int rep = 0; rep < 2; rep++) {
        int eid = tid + rep * 1024;             // 16*128
        int i = eid >> 7, d = eid & 127;
        int row = r0 + i;
        float rr = sigf(G[i * GLD + d]);
        float zz = sigf(G[i * GLD + 128 + d]);
        float nn = tanhf(gbi[i * GB_LD + d] + rr * G[i * GLD + 256 + d]);
        float hold = hprev[(size_t)row * DNF + d];
        hnext[(size_t)row * DNF + d] = (1.0f - zz) * nn + zz * hold;
    }
}

// ---------------------------------------------------------------------------
// k_readout: gate/out GEMMs (K=256, fp16) + sig*tanh + reduce + final fc.
// 64 blocks x 1024 threads. 32 warps = 2 mats x 2 k-halves x 8 frag-groups.
// ---------------------------------------------------------------------------
__global__ void __launch_bounds__(1024)
k_readout(const float* __restrict__ hfin, const float* __restrict__ h0,
          const float* __restrict__ b_gate, const float* __restrict__ b_out,
          const float* __restrict__ w_embed, const float* __restrict__ edge,
          const float* __restrict__ w_fc, const float* __restrict__ b_fc,
          float* __restrict__ out) {
    __shared__ __align__(16) float sbuf[2 * 16 * GB_LD];  // fp16 tiles; later gp|op
    __shared__ float red[16 * 32 * 9];
    __shared__ float sred[1024];
    __shared__ float sgv[128], see[128];
    __shared__ int   s_last;

    __half* hA0 = (__half*)sbuf;               // 16 x ALD halves
    __half* hA1 = (__half*)sbuf + 16 * ALD;
    float* gp  = sbuf;                          // alias (after MMA sync)
    float* op  = sbuf + 16 * GB_LD;

    const int tid  = threadIdx.x;
    const int lane = tid & 31;
    const int w    = tid >> 5;              // 32 warps
    const int fg   = w & 7;
    const int mat  = (w >> 3) & 1;
    const int kh   = w >> 4;
    const int q    = lane >> 2, r = lane & 3;
    const int r0   = blockIdx.x * 16;

    {
        const float* src = (w < 16) ? hfin : h0;
        __half* dst = (w < 16) ? hA0 : hA1;
        int row = r0 + (w & 15);
        float4 v = *(const float4*)(src + (size_t)row * DNF + lane * 4);
        __half2* rp = (__half2*)(dst + (w & 15) * ALD);
        rp[lane * 2]     = __floats2half2_rn(v.x, v.y);
        rp[lane * 2 + 1] = __floats2half2_rn(v.z, v.w);
    }
    __syncthreads();

    const uint4* bp = (const uint4*)(mat ? g_woH : g_wgH);
    const unsigned* Aw = (const unsigned*)(kh ? hA1 : hA0);

    float acc[2][4];
#pragma unroll
    for (int j = 0; j < 2; j++)
#pragma unroll
        for (int c = 0; c < 4; c++) acc[j][c] = 0.f;

    uint4 bf[2][2];
#pragma unroll
    for (int j = 0; j < 2; j++)
        bf[0][j] = bp[((kh * 4) * 16 + fg * 2 + j) * 32 + lane];

#pragma unroll
    for (int kk = 0; kk < 4; kk++) {
        const int u = kh * 4 + kk;
        const int cur = kk & 1, nxt = cur ^ 1;
        if (kk < 3) {
#pragma unroll
            for (int j = 0; j < 2; j++)
                bf[nxt][j] = bp[((u + 1) * 16 + fg * 2 + j) * 32 + lane];
        }
#pragma unroll
        for (int tk = 0; tk < 2; tk++) {
            const int off = (kk * 2 + tk) * 8;     // local k within tile
            unsigned a0 = Aw[q * 68 + off + r];
            unsigned a1 = Aw[(q + 8) * 68 + off + r];
            unsigned a2 = Aw[q * 68 + off + 4 + r];
            unsigned a3 = Aw[(q + 8) * 68 + off + 4 + r];
#pragma unroll
            for (int j = 0; j < 2; j++) {
                unsigned b0 = tk ? bf[cur][j].z : bf[cur][j].x;
                unsigned b1 = tk ? bf[cur][j].w : bf[cur][j].y;
                mma_f16(acc[j], a0, a1, a2, a3, b0, b1);
            }
        }
    }

    if (kh == 1) {
        float* rp = red + ((mat * 8 + fg) * 32 + lane) * 9;
#pragma unroll
        for (int j = 0; j < 2; j++)
#pragma unroll
            for (int c = 0; c < 4; c++) rp[j * 4 + c] = acc[j][c];
    }
    __syncthreads();
    if (kh == 0) {
        const float* rp = red + ((mat * 8 + fg) * 32 + lane) * 9;
        float* dst = mat ? op : gp;
        const float* bias = mat ? b_out : b_gate;
#pragma unroll
        for (int j = 0; j < 2; j++) {
#pragma unroll
            for (int c = 0; c < 4; c++) acc[j][c] += rp[j * 4 + c];
            int col = (fg * 2 + j) * 8 + 2 * r;
            float b0 = bias[col], b1 = bias[col + 1];
            dst[q * GB_LD + col]           = acc[j][0] + b0;
            dst[q * GB_LD + col + 1]       = acc[j][1] + b1;
            dst[(q + 8) * GB_LD + col]     = acc[j][2] + b0;
            dst[(q + 8) * GB_LD + col + 1] = acc[j][3] + b1;
        }
    }
    __syncthreads();

    {
        int grp = tid >> 7, d = tid & 127;
        float a = 0.f;
#pragma unroll
        for (int i = grp * 2; i < grp * 2 + 2; i++)
            a += sigf(gp[i * GB_LD + d]) * tanhf(op[i * GB_LD + d]);
        sred[tid] = a;
    }
    __syncthreads();
    if (tid < 128) {
        float s = 0.f;
#pragma unroll
        for (int g = 0; g < 8; g++) s += sred[g * 128 + tid];
        g_part[blockIdx.x * DNF + tid] = s;
    }
    __syncthreads();

    if (tid == 0) {
        __threadfence();
        int old = atomicAdd(&g_rc, 1);
        s_last = (old == 63) ? 1 : 0;
    }
    __syncthreads();
    if (s_last) {
        if (tid == 0) g_rc = 0;
        if (tid < 128) {
            float gv = 0.f;
            for (int b = 0; b < 64; b++) gv += g_part[b * DNF + tid];
            sgv[tid] = gv;
            float ee = 0.f;
#pragma unroll
            for (int f = 0; f < 5; f++) ee += w_embed[tid * 5 + f] * edge[f];
            see[tid] = ee;
        }
        __syncthreads();
        if (tid < 128) {
            float acc2 = b_fc[tid];
            const float* wr = w_fc + (size_t)tid * 256;
            for (int k = 0; k < 128; k++) acc2 += wr[k] * sgv[k];
            for (int k = 0; k < 128; k++) acc2 += wr[128 + k] * see[k];
            out[tid] = acc2;
        }
    }
}

// ---------------------------------------------------------------------------
extern "C" void kernel_launch(void* const* d_in, const int* in_sizes, int n_in,
                              void* d_out, int out_size) {
    const float* h_in    = (const float*)d_in[0];
    const float* e       = (const float*)d_in[1];
    const float* adj     = (const float*)d_in[2];
    const float* edge    = (const float*)d_in[3];
    const float* w_msg_h = (const float*)d_in[4];
    const float* w_msg_e = (const float*)d_in[5];
    const float* b_msg   = (const float*)d_in[6];
    const float* w_ih    = (const float*)d_in[7];
    const float* w_hh    = (const float*)d_in[8];
    const float* b_ih    = (const float*)d_in[9];
    const float* b_hh    = (const float*)d_in[10];
    const float* w_gate  = (const float*)d_in[11];
    const float* b_gate  = (const float*)d_in[12];
    const float* w_out   = (const float*)d_in[13];
    const float* b_out   = (const float*)d_in[14];
    const float* w_embed = (const float*)d_in[15];
    const float* w_fc    = (const float*)d_in[16];
    const float* b_fc    = (const float*)d_in[17];
    float* out = (float*)d_out;

    float *p_ha, *p_hb;
    cudaGetSymbolAddress((void**)&p_ha, g_ha);
    cudaGetSymbolAddress((void**)&p_hb, g_hb);

    k_setup<<<NN + 497, 256>>>(adj, e, w_msg_h, w_msg_e, w_ih, b_msg,
                               w_hh, w_gate, w_out);
    k_cei<<<64, 1024>>>();
    k_layer<<<64, 1024>>>(h_in, p_ha, b_ih, b_hh);
    k_layer<<<64, 1024>>>(p_ha, p_hb, b_ih, b_hh);
    k_layer<<<64, 1024>>>(p_hb, p_ha, b_ih, b_hh);
    k_layer<<<64, 1024>>>(p_ha, p_hb, b_ih, b_hh);
    k_readout<<<64, 1024>>>(p_hb, h_in, b_gate, b_out, w_embed, edge,
                            w_fc, b_fc, out);
}

// round 12
// speedup vs baseline: 1.2464x; 1.0013x over previous
#include <cuda_runtime.h>
#include <cuda_fp16.h>
#include <math.h>

#define NN   1024
#define DNF  128
#define G3   384
#define ALD  136     // fp16 A-tile stride in halves (68 words)
#define GLD  388     // gate buffer stride: 384 + 4 pad
#define GB_LD 132
#define LOG2E 1.4426950408889634f

// ---------------- device scratch ----------------
__device__ float g_er  [NN * DNF];
__device__ float g_cei [NN * G3];
__device__ float g_ha  [NN * DNF];
__device__ float g_hb  [NN * DNF];
__device__ __half g_wimH[G3 * DNF];
__device__ __half g_wieH[G3 * DNF];
__device__ __half g_whhH[G3 * DNF];
__device__ __half g_wgH [DNF * 256];
__device__ __half g_woH [DNF * 256];
__device__ float g_bvec[G3];
__device__ int2  g_nze [NN * NN];       // interleaved {idx, val-bits}
__device__ int   g_nzc [NN];
__device__ float g_part[64 * DNF];
__device__ int   g_rc;

// ---------------- fast transcendentals (accurate: ex2/rcp ~2^-22) --------
__device__ __forceinline__ float fex2(float x) {
    float r; asm("ex2.approx.f32 %0, %1;" : "=f"(r) : "f"(x)); return r;
}
__device__ __forceinline__ float frcp(float x) {
    float r; asm("rcp.approx.f32 %0, %1;" : "=f"(r) : "f"(x)); return r;
}
__device__ __forceinline__ float sigf(float x) {
    return frcp(1.0f + fex2(-x * LOG2E));
}
__device__ __forceinline__ float tanhf_fast(float x) {
    return 1.0f - 2.0f * frcp(1.0f + fex2(x * (2.0f * LOG2E)));
}

__device__ __forceinline__ void mma_f16(float* c,
                                        unsigned a0, unsigned a1,
                                        unsigned a2, unsigned a3,
                                        unsigned b0, unsigned b1) {
    asm volatile(
        "mma.sync.aligned.m16n8k16.row.col.f32.f16.f16.f32 "
        "{%0,%1,%2,%3}, {%4,%5,%6,%7}, {%8,%9}, {%0,%1,%2,%3};"
        : "+f"(c[0]), "+f"(c[1]), "+f"(c[2]), "+f"(c[3])
        : "r"(a0), "r"(a1), "r"(a2), "r"(a3), "r"(b0), "r"(b1));
}

// fp16 frag-packed index (see round-11 layout)
__device__ __forceinline__ int hidx(int n, int k, int nfr) {
    int f = n >> 3, q = n & 7;
    int t = k >> 4, kk = k & 15;
    int half = kk >> 3;
    int r = (kk & 7) >> 1;
    int lo = kk & 1;
    int u = t >> 1, tk = t & 1;
    return ((((u * nfr + f) * 32 + q * 4 + r) * 4) + tk * 2 + half) * 2 + lo;
}

// strided warp gather (stride 2, start = half) over interleaved (idx,val)
__device__ __forceinline__ float4 gather_half(const float* __restrict__ src,
                                              const int2* __restrict__ ep,
                                              int cnt, int lane, int half) {
    float4 acc = make_float4(0.f, 0.f, 0.f, 0.f);
    int k = half;
    for (; k + 6 < cnt; k += 8) {
        int2 e0 = ep[k], e1 = ep[k + 2], e2 = ep[k + 4], e3 = ep[k + 6];
        float w0 = __int_as_float(e0.y), w1 = __int_as_float(e1.y);
        float w2 = __int_as_float(e2.y), w3 = __int_as_float(e3.y);
        float4 a0 = *(const float4*)(src + (size_t)e0.x * DNF + lane * 4);
        float4 a1 = *(const float4*)(src + (size_t)e1.x * DNF + lane * 4);
        float4 a2 = *(const float4*)(src + (size_t)e2.x * DNF + lane * 4);
        float4 a3 = *(const float4*)(src + (size_t)e3.x * DNF + lane * 4);
        acc.x += w0*a0.x + w1*a1.x + w2*a2.x + w3*a3.x;
        acc.y += w0*a0.y + w1*a1.y + w2*a2.y + w3*a3.y;
        acc.z += w0*a0.z + w1*a1.z + w2*a2.z + w3*a3.z;
        acc.w += w0*a0.w + w1*a1.w + w2*a2.w + w3*a3.w;
    }
    for (; k < cnt; k += 2) {
        int2 e = ep[k];
        float w = __int_as_float(e.y);
        float4 av = *(const float4*)(src + (size_t)e.x * DNF + lane * 4);
        acc.x += w*av.x; acc.y += w*av.y; acc.z += w*av.z; acc.w += w*av.w;
    }
    return acc;
}

// ---------------------------------------------------------------------------
// k_setup: bid<1024 — adjacency compaction + er; bid>=1024 — weight
// products (wim, wie), fp16 packing (whh, wgate, wout), bvec.   256 threads.
// ---------------------------------------------------------------------------
__global__ void __launch_bounds__(256)
k_setup(const float* __restrict__ adj, const float* __restrict__ e,
        const float* __restrict__ w_msg_h, const float* __restrict__ w_msg_e,
        const float* __restrict__ w_ih, const float* __restrict__ b_msg,
        const float* __restrict__ w_hh, const float* __restrict__ w_gate,
        const float* __restrict__ w_out) {
    const int bid = blockIdx.x;
    const int tid = threadIdx.x;

    if (bid < NN) {
        const int i    = bid;
        const int lane = tid & 31;
        const int w    = tid >> 5;

        __shared__ int   s_idx[NN];
        __shared__ float s_val[NN];
        __shared__ int   s_wcnt[8];
        __shared__ int   s_woff[8];
        __shared__ int   s_cnt;
        __shared__ float s_red[8 * DNF];

        const float* arow = adj + (size_t)i * NN;
        const int base = w * 128;

        float av[4]; unsigned mm[4];
#pragma unroll
        for (int c = 0; c < 4; c++) av[c] = arow[base + c * 32 + lane];
        int tot = 0;
#pragma unroll
        for (int c = 0; c < 4; c++) {
            mm[c] = __ballot_sync(0xffffffffu, av[c] != 0.0f);
            tot += __popc(mm[c]);
        }
        if (lane == 0) s_wcnt[w] = tot;
        __syncthreads();
        if (tid == 0) {
            int run = 0;
            for (int ww = 0; ww < 8; ww++) { s_woff[ww] = run; run += s_wcnt[ww]; }
            s_cnt = run;
        }
        __syncthreads();

        int off = s_woff[w];
        const unsigned lm = (1u << lane) - 1u;
#pragma unroll
        for (int c = 0; c < 4; c++) {
            if (av[c] != 0.0f) {
                int p = off + __popc(mm[c] & lm);
                s_idx[p] = base + c * 32 + lane;
                s_val[p] = av[c];
            }
            off += __popc(mm[c]);
        }
        __syncthreads();

        const int cnt = s_cnt;
        if (tid == 0) g_nzc[i] = cnt;
        for (int k = tid; k < cnt; k += 256)
            g_nze[(size_t)i * NN + k] = make_int2(s_idx[k],
                                                  __float_as_int(s_val[k]));

        const int q = tid & 31;
        const int g = tid >> 5;
        const float* ebase = e + (size_t)i * NN * DNF;
        float4 acc = make_float4(0.f, 0.f, 0.f, 0.f);
        for (int k = g; k < cnt; k += 8) {
            float v = s_val[k];
            float4 ev = *(const float4*)(ebase + (size_t)s_idx[k] * DNF + q * 4);
            acc.x += v * ev.x; acc.y += v * ev.y;
            acc.z += v * ev.z; acc.w += v * ev.w;
        }
        s_red[g * DNF + q * 4 + 0] = acc.x;
        s_red[g * DNF + q * 4 + 1] = acc.y;
        s_red[g * DNF + q * 4 + 2] = acc.z;
        s_red[g * DNF + q * 4 + 3] = acc.w;
        __syncthreads();
        if (tid < 128) {
            float s = 0.f;
#pragma unroll
            for (int gg = 0; gg < 8; gg++) s += s_red[gg * DNF + tid];
            g_er[(size_t)i * DNF + tid] = s;
        }
        return;
    }

    const int sid = bid - NN;
    if (sid < 384) {
        const bool is_h = (sid < 192);
        const int  lsid = is_h ? sid : sid - 192;
        const float* B = is_h ? w_msg_h : w_msg_e;
        __half* P = is_h ? g_wimH : g_wieH;
        int id = lsid * 256 + tid;
        int n = id >> 7, k = id & 127;
        float acc = 0.f;
        const float* wr = w_ih + (size_t)n * DNF;
#pragma unroll 4
        for (int d = 0; d < DNF; d++) acc += wr[d] * B[(size_t)d * DNF + k];
        P[hidx(n, k, 48)] = __float2half_rn(acc);
    } else if (sid < 432) {
        int b = sid - 384;
#pragma unroll
        for (int rep = 0; rep < 4; rep++) {
            int eid = b * 1024 + rep * 256 + tid;
            int n = eid >> 7, k = eid & 127;
            g_whhH[hidx(n, k, 48)] = __float2half_rn(w_hh[(size_t)n * DNF + k]);
        }
    } else if (sid < 464) {
        int b = sid - 432;
#pragma unroll
        for (int rep = 0; rep < 4; rep++) {
            int eid = b * 1024 + rep * 256 + tid;
            int n = eid >> 8, k = eid & 255;
            g_wgH[hidx(n, k, 16)] = __float2half_rn(w_gate[(size_t)n * 256 + k]);
        }
    } else if (sid < 496) {
        int b = sid - 464;
#pragma unroll
        for (int rep = 0; rep < 4; rep++) {
            int eid = b * 1024 + rep * 256 + tid;
            int n = eid >> 8, k = eid & 255;
            g_woH[hidx(n, k, 16)] = __float2half_rn(w_out[(size_t)n * 256 + k]);
        }
    } else {
        for (int n = tid; n < G3; n += 256) {
            float acc = 0.f;
            const float* wr = w_ih + (size_t)n * DNF;
            for (int k = 0; k < DNF; k++) acc += wr[k] * b_msg[k];
            g_bvec[n] = acc;
        }
    }
}

// ---------------------------------------------------------------------------
// k_cei: cei = er @ wie^T + bvec.  64 blocks x 1024 threads, fp16 MMA.
// ---------------------------------------------------------------------------
__global__ void __launch_bounds__(1024)
k_cei() {
    __shared__ __align__(16) __half sA[16 * ALD];
    __shared__ float red[16 * 32 * 13];

    const int tid  = threadIdx.x;
    const int lane = tid & 31;
    const int w    = tid >> 5;
    const int nw   = w & 15;
    const int kh   = w >> 4;
    const int q    = lane >> 2, r = lane & 3;
    const int r0   = blockIdx.x * 16;

#pragma unroll
    for (int rep = 0; rep < 2; rep++) {
        int eid = tid + rep * 1024;
        int i = eid >> 7, d = eid & 127;
        sA[i * ALD + d] = __float2half_rn(g_er[(size_t)(r0 + i) * DNF + d]);
    }
    __syncthreads();

    const unsigned* Aw = (const unsigned*)sA;

    float acc[3][4];
#pragma unroll
    for (int j = 0; j < 3; j++)
#pragma unroll
        for (int c = 0; c < 4; c++) acc[j][c] = 0.f;

    const uint4* bp = (const uint4*)g_wieH;

    uint4 bf[2][3];
#pragma unroll
    for (int j = 0; j < 3; j++)
        bf[0][j] = bp[((kh * 2) * 48 + nw * 3 + j) * 32 + lane];

#pragma unroll
    for (int kk = 0; kk < 2; kk++) {
        const int u = kh * 2 + kk;
        const int cur = kk & 1, nxt = cur ^ 1;
        if (kk < 1) {
#pragma unroll
            for (int j = 0; j < 3; j++)
                bf[nxt][j] = bp[((u + 1) * 48 + nw * 3 + j) * 32 + lane];
        }
#pragma unroll
        for (int tk = 0; tk < 2; tk++) {
            const int off = (u * 2 + tk) * 8;
            unsigned a0 = Aw[q * 68 + off + r];
            unsigned a1 = Aw[(q + 8) * 68 + off + r];
            unsigned a2 = Aw[q * 68 + off + 4 + r];
            unsigned a3 = Aw[(q + 8) * 68 + off + 4 + r];
#pragma unroll
            for (int j = 0; j < 3; j++) {
                unsigned b0 = tk ? bf[cur][j].z : bf[cur][j].x;
                unsigned b1 = tk ? bf[cur][j].w : bf[cur][j].y;
                mma_f16(acc[j], a0, a1, a2, a3, b0, b1);
            }
        }
    }

    if (kh == 1) {
        float* rp = red + (nw * 32 + lane) * 13;
#pragma unroll
        for (int j = 0; j < 3; j++)
#pragma unroll
            for (int c = 0; c < 4; c++) rp[j * 4 + c] = acc[j][c];
    }
    __syncthreads();
    if (kh == 0) {
        const float* rp = red + (nw * 32 + lane) * 13;
#pragma unroll
        for (int j = 0; j < 3; j++) {
#pragma unroll
            for (int c = 0; c < 4; c++) acc[j][c] += rp[j * 4 + c];
            int col = (nw * 3 + j) * 8 + 2 * r;
            float bv0 = g_bvec[col], bv1 = g_bvec[col + 1];
            *(float2*)(g_cei + (size_t)(r0 + q) * G3 + col) =
                make_float2(acc[j][0] + bv0, acc[j][1] + bv1);
            *(float2*)(g_cei + (size_t)(r0 + q + 8) * G3 + col) =
                make_float2(acc[j][2] + bv0, acc[j][3] + bv1);
        }
    }
}

// ---------------------------------------------------------------------------
// k_layer: fused spmv + dual fp16 GEMM + GRU for 16 rows. 64 blocks x 1024 thr.
// ---------------------------------------------------------------------------
__global__ void __launch_bounds__(1024)
k_layer(const float* __restrict__ hprev, float* __restrict__ hnext,
        const float* __restrict__ b_ih, const float* __restrict__ b_hh) {
    __shared__ __align__(16) __half sAh[2 * 16 * ALD];  // sh | hh ; later gbi
    __shared__ __align__(16) float G[16 * GLD];         // first: ph[32][32] f4

    __half* shA = sAh;
    __half* hhA = sAh + 16 * ALD;
    float*  gbi = (float*)sAh;
    float4* ph  = (float4*)G;

    const int tid  = threadIdx.x;
    const int lane = tid & 31;
    const int w    = tid >> 5;
    const int q    = lane >> 2, r = lane & 3;
    const int r0   = blockIdx.x * 16;

    // ---- phase 1a: strided gather halves (2 warps per row) ----
    {
        const int row  = r0 + (w & 15);
        const int half = w >> 4;
        const int cnt  = g_nzc[row];
        const int2* ep = g_nze + (size_t)row * NN;
        ph[w * 32 + lane] = gather_half(hprev, ep, cnt, lane, half);
    }
    __syncthreads();

    // ---- phase 1b: combine halves -> shA (fp16) ; stage h -> hhA (fp16) ----
    if (w < 16) {
        float4 a = ph[w * 32 + lane];
        float4 b = ph[(w + 16) * 32 + lane];
        __half2* rp = (__half2*)(shA + w * ALD);
        rp[lane * 2]     = __floats2half2_rn(a.x + b.x, a.y + b.y);
        rp[lane * 2 + 1] = __floats2half2_rn(a.z + b.z, a.w + b.w);
    } else {
        int row = r0 + (w - 16);
        float4 hv = *(const float4*)(hprev + (size_t)row * DNF + lane * 4);
        __half2* rp = (__half2*)(hhA + (w - 16) * ALD);
        rp[lane * 2]     = __floats2half2_rn(hv.x, hv.y);
        rp[lane * 2 + 1] = __floats2half2_rn(hv.z, hv.w);
    }
    __syncthreads();

    // ---- phase 2: MMA (mat 0: gi = sh@wim^T ; mat 1: gh = h@whh^T) ----
    const int mat = w >> 4;
    const int nw  = w & 15;
    const unsigned* Aw = (const unsigned*)(mat ? hhA : shA);
    const uint4* bp = (const uint4*)(mat ? g_whhH : g_wimH);

    float acc[3][4];
#pragma unroll
    for (int j = 0; j < 3; j++)
#pragma unroll
        for (int c = 0; c < 4; c++) acc[j][c] = 0.f;

    uint4 bf[2][3];
#pragma unroll
    for (int j = 0; j < 3; j++)
        bf[0][j] = bp[(0 * 48 + nw * 3 + j) * 32 + lane];

#pragma unroll
    for (int u = 0; u < 4; u++) {
        const int cur = u & 1, nxt = cur ^ 1;
        if (u < 3) {
#pragma unroll
            for (int j = 0; j < 3; j++)
                bf[nxt][j] = bp[((u + 1) * 48 + nw * 3 + j) * 32 + lane];
        }
#pragma unroll
        for (int tk = 0; tk < 2; tk++) {
            const int off = (u * 2 + tk) * 8;
            unsigned a0 = Aw[q * 68 + off + r];
            unsigned a1 = Aw[(q + 8) * 68 + off + r];
            unsigned a2 = Aw[q * 68 + off + 4 + r];
            unsigned a3 = Aw[(q + 8) * 68 + off + 4 + r];
#pragma unroll
            for (int j = 0; j < 3; j++) {
                unsigned b0 = tk ? bf[cur][j].z : bf[cur][j].x;
                unsigned b1 = tk ? bf[cur][j].w : bf[cur][j].y;
                mma_f16(acc[j], a0, a1, a2, a3, b0, b1);
            }
        }
    }

    // gh warps: write gh + b_hh into G (ph already consumed)
    if (mat == 1) {
#pragma unroll
        for (int j = 0; j < 3; j++) {
            int col = (nw * 3 + j) * 8 + 2 * r;
            float b0 = b_hh[col], b1 = b_hh[col + 1];
            G[q * GLD + col]           = acc[j][0] + b0;
            G[q * GLD + col + 1]       = acc[j][1] + b1;
            G[(q + 8) * GLD + col]     = acc[j][2] + b0;
            G[(q + 8) * GLD + col + 1] = acc[j][3] + b1;
        }
    }
    __syncthreads();

    // gi warps: combine with cei + b_ih
    if (mat == 0) {
#pragma unroll
        for (int j = 0; j < 3; j++) {
            int col = (nw * 3 + j) * 8 + 2 * r;
            float bi0 = b_ih[col], bi1 = b_ih[col + 1];
#pragma unroll
            for (int s = 0; s < 2; s++) {
                int i = q + s * 8;
                int row = r0 + i;
                float2 ce = *(const float2*)(g_cei + (size_t)row * G3 + col);
                float gi0 = acc[j][s * 2 + 0] + ce.x + bi0;
                float gi1 = acc[j][s * 2 + 1] + ce.y + bi1;
                if (col < 256) {
                    G[i * GLD + col]     += gi0;
                    G[i * GLD + col + 1] += gi1;
                } else {
                    gbi[i * GB_LD + (col - 256)]     = gi0;
                    gbi[i * GB_LD + (col - 256) + 1] = gi1;
                }
            }
        }
    }
    __syncthreads();

    // ---- GRU (fast transcendentals) ----
#pragma unroll
    for (int rep = 0; rep < 2; rep++) {
        int eid = tid + rep * 1024;
        int i = eid >> 7, d = eid & 127;
        int row = r0 + i;
        float rr = sigf(G[i * GLD + d]);
        float zz = sigf(G[i * GLD + 128 + d]);
        float nn = tanhf_fast(gbi[i * GB_LD + d] + rr * G[i * GLD + 256 + d]);
        float hold = hprev[(size_t)row * DNF + d];
        hnext[(size_t)row * DNF + d] = (1.0f - zz) * nn + zz * hold;
    }
}

// ---------------------------------------------------------------------------
// k_readout: gate/out GEMMs (K=256, fp16) + sig*tanh + reduce + final fc.
// ---------------------------------------------------------------------------
__global__ void __launch_bounds__(1024)
k_readout(const float* __restrict__ hfin, const float* __restrict__ h0,
          const float* __restrict__ b_gate, const float* __restrict__ b_out,
          const float* __restrict__ w_embed, const float* __restrict__ edge,
          const float* __restrict__ w_fc, const float* __restrict__ b_fc,
          float* __restrict__ out) {
    __shared__ __align__(16) float sbuf[2 * 16 * GB_LD];
    __shared__ float red[16 * 32 * 9];
    __shared__ float sred[1024];
    __shared__ float sgv[128], see[128];
    __shared__ int   s_last;

    __half* hA0 = (__half*)sbuf;
    __half* hA1 = (__half*)sbuf + 16 * ALD;
    float* gp  = sbuf;
    float* op  = sbuf + 16 * GB_LD;

    const int tid  = threadIdx.x;
    const int lane = tid & 31;
    const int w    = tid >> 5;
    const int fg   = w & 7;
    const int mat  = (w >> 3) & 1;
    const int kh   = w >> 4;
    const int q    = lane >> 2, r = lane & 3;
    const int r0   = blockIdx.x * 16;

    {
        const float* src = (w < 16) ? hfin : h0;
        __half* dst = (w < 16) ? hA0 : hA1;
        int row = r0 + (w & 15);
        float4 v = *(const float4*)(src + (size_t)row * DNF + lane * 4);
        __half2* rp = (__half2*)(dst + (w & 15) * ALD);
        rp[lane * 2]     = __floats2half2_rn(v.x, v.y);
        rp[lane * 2 + 1] = __floats2half2_rn(v.z, v.w);
    }
    __syncthreads();

    const uint4* bp = (const uint4*)(mat ? g_woH : g_wgH);
    const unsigned* Aw = (const unsigned*)(kh ? hA1 : hA0);

    float acc[2][4];
#pragma unroll
    for (int j = 0; j < 2; j++)
#pragma unroll
        for (int c = 0; c < 4; c++) acc[j][c] = 0.f;

    uint4 bf[2][2];
#pragma unroll
    for (int j = 0; j < 2; j++)
        bf[0][j] = bp[((kh * 4) * 16 + fg * 2 + j) * 32 + lane];

#pragma unroll
    for (int kk = 0; kk < 4; kk++) {
        const int u = kh * 4 + kk;
        const int cur = kk & 1, nxt = cur ^ 1;
        if (kk < 3) {
#pragma unroll
            for (int j = 0; j < 2; j++)
                bf[nxt][j] = bp[((u + 1) * 16 + fg * 2 + j) * 32 + lane];
        }
#pragma unroll
        for (int tk = 0; tk < 2; tk++) {
            const int off = (kk * 2 + tk) * 8;
            unsigned a0 = Aw[q * 68 + off + r];
            unsigned a1 = Aw[(q + 8) * 68 + off + r];
            unsigned a2 = Aw[q * 68 + off + 4 + r];
            unsigned a3 = Aw[(q + 8) * 68 + off + 4 + r];
#pragma unroll
            for (int j = 0; j < 2; j++) {
                unsigned b0 = tk ? bf[cur][j].z : bf[cur][j].x;
                unsigned b1 = tk ? bf[cur][j].w : bf[cur][j].y;
                mma_f16(acc[j], a0, a1, a2, a3, b0, b1);
            }
        }
    }

    if (kh == 1) {
        float* rp = red + ((mat * 8 + fg) * 32 + lane) * 9;
#pragma unroll
        for (int j = 0; j < 2; j++)
#pragma unroll
            for (int c = 0; c < 4; c++) rp[j * 4 + c] = acc[j][c];
    }
    __syncthreads();
    if (kh == 0) {
        const float* rp = red + ((mat * 8 + fg) * 32 + lane) * 9;
        float* dst = mat ? op : gp;
        const float* bias = mat ? b_out : b_gate;
#pragma unroll
        for (int j = 0; j < 2; j++) {
#pragma unroll
            for (int c = 0; c < 4; c++) acc[j][c] += rp[j * 4 + c];
            int col = (fg * 2 + j) * 8 + 2 * r;
            float b0 = bias[col], b1 = bias[col + 1];
            dst[q * GB_LD + col]           = acc[j][0] + b0;
            dst[q * GB_LD + col + 1]       = acc[j][1] + b1;
            dst[(q + 8) * GB_LD + col]     = acc[j][2] + b0;
            dst[(q + 8) * GB_LD + col + 1] = acc[j][3] + b1;
        }
    }
    __syncthreads();

    {
        int grp = tid >> 7, d = tid & 127;
        float a = 0.f;
#pragma unroll
        for (int i = grp * 2; i < grp * 2 + 2; i++)
            a += sigf(gp[i * GB_LD + d]) * tanhf_fast(op[i * GB_LD + d]);
        sred[tid] = a;
    }
    __syncthreads();
    if (tid < 128) {
        float s = 0.f;
#pragma unroll
        for (int g = 0; g < 8; g++) s += sred[g * 128 + tid];
        g_part[blockIdx.x * DNF + tid] = s;
    }
    __syncthreads();

    if (tid == 0) {
        __threadfence();
        int old = atomicAdd(&g_rc, 1);
        s_last = (old == 63) ? 1 : 0;
    }
    __syncthreads();
    if (s_last) {
        if (tid == 0) g_rc = 0;
        if (tid < 128) {
            float gv = 0.f;
            for (int b = 0; b < 64; b++) gv += g_part[b * DNF + tid];
            sgv[tid] = gv;
            float ee = 0.f;
#pragma unroll
            for (int f = 0; f < 5; f++) ee += w_embed[tid * 5 + f] * edge[f];
            see[tid] = ee;
        }
        __syncthreads();
        if (tid < 128) {
            float acc2 = b_fc[tid];
            const float* wr = w_fc + (size_t)tid * 256;
            for (int k = 0; k < 128; k++) acc2 += wr[k] * sgv[k];
            for (int k = 0; k < 128; k++) acc2 += wr[128 + k] * see[k];
            out[tid] = acc2;
        }
    }
}

// ---------------------------------------------------------------------------
extern "C" void kernel_launch(void* const* d_in, const int* in_sizes, int n_in,
                              void* d_out, int out_size) {
    const float* h_in    = (const float*)d_in[0];
    const float* e       = (const float*)d_in[1];
    const float* adj     = (const float*)d_in[2];
    const float* edge    = (const float*)d_in[3];
    const float* w_msg_h = (const float*)d_in[4];
    const float* w_msg_e = (const float*)d_in[5];
    const float* b_msg   = (const float*)d_in[6];
    const float* w_ih    = (const float*)d_in[7];
    const float* w_hh    = (const float*)d_in[8];
    const float* b_ih    = (const float*)d_in[9];
    const float* b_hh    = (const float*)d_in[10];
    const float* w_gate  = (const float*)d_in[11];
    const float* b_gate  = (const float*)d_in[12];
    const float* w_out   = (const float*)d_in[13];
    const float* b_out   = (const float*)d_in[14];
    const float* w_embed = (const float*)d_in[15];
    const float* w_fc    = (const float*)d_in[16];
    const float* b_fc    = (const float*)d_in[17];
    float* out = (float*)d_out;

    float *p_ha, *p_hb;
    cudaGetSymbolAddress((void**)&p_ha, g_ha);
    cudaGetSymbolAddress((void**)&p_hb, g_hb);

    k_setup<<<NN + 497, 256>>>(adj, e, w_msg_h, w_msg_e, w_ih, b_msg,
                               w_hh, w_gate, w_out);
    k_cei<<<64, 1024>>>();
    k_layer<<<64, 1024>>>(h_in, p_ha, b_ih, b_hh);
    k_layer<<<64, 1024>>>(p_ha, p_hb, b_ih, b_hh);
    k_layer<<<64, 1024>>>(p_hb, p_ha, b_ih, b_hh);
    k_layer<<<64, 1024>>>(p_ha, p_hb, b_ih, b_hh);
    k_readout<<<64, 1024>>>(p_hb, h_in, b_gate, b_out, w_embed, edge,
                            w_fc, b_fc, out);
}